// round 10
// baseline (speedup 1.0000x reference)
#include <cuda_runtime.h>
#include <cuda_bf16.h>
#include <cstdint>

#define NNODES 200000
#define NEDGES 600000
#define NCH    128
#define SK     136            // padded bf16 row stride
#define SKB    (SK * 2)
#define CHUNK  512
#define NCHUNK ((NNODES + CHUNK - 1) / CHUNK)   // 391

// ---------------- scratch ----------------
__device__ float g_h[(size_t)NNODES * NCH];
__device__ float g_acc[(size_t)NNODES * NCH];
__device__ float g_dinv[NNODES];
__device__ int   g_indeg[NNODES];
__device__ int   g_cursor[NNODES];
__device__ int   g_rowptr[NNODES];
__device__ int   g_bsum[CHUNK];
__device__ int   g_bbase[CHUNK];
__device__ int   g_esrc[NEDGES];
__device__ float g_sum[NCH];
__device__ float g_sumsq[NCH];
__device__ float g_scale[NCH];
__device__ float g_shift[NCH];
__device__ __nv_bfloat16 g_Wt[4][NCH * NCH];   // W1hi W1lo W2hi W2lo, [n][k]

// ---------------- prep ----------------
__global__ void k_convW(const float* __restrict__ W1, const float* __restrict__ W2) {
    int idx = blockIdx.x * blockDim.x + threadIdx.x;
    if (idx < NCH) { g_sum[idx] = 0.f; g_sumsq[idx] = 0.f; }
    if (idx >= NCH * NCH) return;
    int nn = idx & 127, kk = idx >> 7;
    int o = nn * NCH + kk;
    float v1 = W1[idx], v2 = W2[idx];
    __nv_bfloat16 h1 = __float2bfloat16(v1);
    __nv_bfloat16 h2 = __float2bfloat16(v2);
    g_Wt[0][o] = h1; g_Wt[1][o] = __float2bfloat16(v1 - __bfloat162float(h1));
    g_Wt[2][o] = h2; g_Wt[3][o] = __float2bfloat16(v2 - __bfloat162float(h2));
}

__global__ void k_stats(const float* __restrict__ x, const float* __restrict__ aP, int n) {
    __shared__ float4 rs[8][32];
    __shared__ float4 rq[8][32];
    int tid = threadIdx.x, c4 = tid & 31, ry = tid >> 5;
    float av = aP[0];
    float4 s = make_float4(0, 0, 0, 0), q = make_float4(0, 0, 0, 0);
    for (int base = blockIdx.x * 32; base < n; base += gridDim.x * 32) {
#pragma unroll
        for (int u = 0; u < 4; u++) {
            int r = base + ry + u * 8;
            if (r < n) {
                float4 v = ((const float4*)x)[(size_t)r * 32 + c4];
                v.x = v.x >= 0.f ? v.x : av * v.x;
                v.y = v.y >= 0.f ? v.y : av * v.y;
                v.z = v.z >= 0.f ? v.z : av * v.z;
                v.w = v.w >= 0.f ? v.w : av * v.w;
                s.x += v.x; s.y += v.y; s.z += v.z; s.w += v.w;
                q.x += v.x * v.x; q.y += v.y * v.y; q.z += v.z * v.z; q.w += v.w * v.w;
            }
        }
    }
    rs[ry][c4] = s; rq[ry][c4] = q;
    __syncthreads();
    if (ry == 0) {
        float4 S = rs[0][c4], Q = rq[0][c4];
#pragma unroll
        for (int i = 1; i < 8; i++) {
            float4 a = rs[i][c4], b = rq[i][c4];
            S.x += a.x; S.y += a.y; S.z += a.z; S.w += a.w;
            Q.x += b.x; Q.y += b.y; Q.z += b.z; Q.w += b.w;
        }
        atomicAdd(&g_sum[c4 * 4 + 0], S.x); atomicAdd(&g_sum[c4 * 4 + 1], S.y);
        atomicAdd(&g_sum[c4 * 4 + 2], S.z); atomicAdd(&g_sum[c4 * 4 + 3], S.w);
        atomicAdd(&g_sumsq[c4 * 4 + 0], Q.x); atomicAdd(&g_sumsq[c4 * 4 + 1], Q.y);
        atomicAdd(&g_sumsq[c4 * 4 + 2], Q.z); atomicAdd(&g_sumsq[c4 * 4 + 3], Q.w);
    }
}

__global__ void k_finalize(const float* __restrict__ gamma, const float* __restrict__ beta, int n) {
    int c = threadIdx.x;
    if (c >= NCH) return;
    float invn = 1.0f / (float)n;
    float mean = g_sum[c] * invn;
    float var  = g_sumsq[c] * invn - mean * mean;
    float sc   = gamma[c] * rsqrtf(var + 1e-5f);
    g_scale[c] = sc;
    g_shift[c] = beta[c] - mean * sc;
}

__global__ void k_zero(int n) {
    int i = blockIdx.x * blockDim.x + threadIdx.x;
    if (i < n) { g_indeg[i] = 0; g_cursor[i] = 0; }
}
__global__ void k_count(const int* __restrict__ dst, int e) {
    int i = blockIdx.x * blockDim.x + threadIdx.x;
    if (i < e) atomicAdd(&g_indeg[dst[i]], 1);
}
__global__ void k_dinv(int n) {
    int i = blockIdx.x * blockDim.x + threadIdx.x;
    if (i < n) g_dinv[i] = rsqrtf((float)(g_indeg[i] + 1));
}

__global__ void k_scan1(int n) {
    __shared__ int sh[CHUNK];
    int i = blockIdx.x * CHUNK + threadIdx.x;
    sh[threadIdx.x] = (i < n) ? g_indeg[i] : 0;
    __syncthreads();
    for (int s = CHUNK / 2; s > 0; s >>= 1) {
        if (threadIdx.x < s) sh[threadIdx.x] += sh[threadIdx.x + s];
        __syncthreads();
    }
    if (threadIdx.x == 0) g_bsum[blockIdx.x] = sh[0];
}
__global__ void k_scan2() {
    __shared__ int sh[CHUNK];
    int t = threadIdx.x;
    sh[t] = (t < NCHUNK) ? g_bsum[t] : 0;
    __syncthreads();
    for (int d = 1; d < CHUNK; d <<= 1) {
        int v = (t >= d) ? sh[t - d] : 0;
        __syncthreads();
        sh[t] += v;
        __syncthreads();
    }
    if (t < NCHUNK) g_bbase[t] = (t == 0) ? 0 : sh[t - 1];
}
__global__ void k_scan3(int n) {
    __shared__ int sh[CHUNK];
    int t = threadIdx.x;
    int i = blockIdx.x * CHUNK + t;
    int v0 = (i < n) ? g_indeg[i] : 0;
    sh[t] = v0;
    __syncthreads();
    for (int d = 1; d < CHUNK; d <<= 1) {
        int v = (t >= d) ? sh[t - d] : 0;
        __syncthreads();
        sh[t] += v;
        __syncthreads();
    }
    if (i < n) g_rowptr[i] = g_bbase[blockIdx.x] + sh[t] - v0;
}
__global__ void k_fill(const int* __restrict__ src, const int* __restrict__ dst, int e) {
    int i = blockIdx.x * blockDim.x + threadIdx.x;
    if (i >= e) return;
    int d = dst[i];
    int pos = g_rowptr[d] + atomicAdd(&g_cursor[d], 1);
    g_esrc[pos] = src[i];
}

// ---------------- HMMA helpers ----------------
__device__ __forceinline__ void mma16816(float* c, const uint32_t* a, const uint32_t* b) {
    asm volatile(
        "mma.sync.aligned.m16n8k16.row.col.f32.bf16.bf16.f32 "
        "{%0,%1,%2,%3}, {%4,%5,%6,%7}, {%8,%9}, {%0,%1,%2,%3};"
        : "+f"(c[0]), "+f"(c[1]), "+f"(c[2]), "+f"(c[3])
        : "r"(a[0]), "r"(a[1]), "r"(a[2]), "r"(a[3]), "r"(b[0]), "r"(b[1]));
}
__device__ __forceinline__ void ldsm4(uint32_t* r, uint32_t addr) {
    asm volatile("ldmatrix.sync.aligned.m8n8.x4.shared.b16 {%0,%1,%2,%3}, [%4];"
                 : "=r"(r[0]), "=r"(r[1]), "=r"(r[2]), "=r"(r[3]) : "r"(addr));
}
__device__ __forceinline__ uint32_t pack_bf2(float x, float y) {
    __nv_bfloat162 h = __floats2bfloat162_rn(x, y);
    return *(uint32_t*)&h;
}

// ---------------- GEMM: g_h = f(A) @ W  (M-tile 64, 2 CTAs/SM) ----------------
// 8 warps: m-warp = warp&1 (32 rows each), n-warp = warp>>1 (32 cols each).
template <int MODE>
__global__ void __launch_bounds__(256, 2)
k_mma(const float* __restrict__ Ain,
      const __nv_bfloat16* __restrict__ Whi, const __nv_bfloat16* __restrict__ Wlo,
      const float* __restrict__ aP, int n)
{
    extern __shared__ char sm[];
    const int AH = 0, AL = 64 * SKB, WH = 2 * 64 * SKB, WL = WH + 128 * SKB;
    int tid = threadIdx.x;
    float av = aP[0];
    int row0 = blockIdx.x * 64;

    // ---- A tile: 64 rows; thread -> (row = tid>>2, quarter = tid&3), 8 float4 each ----
    {
        int rl = tid >> 2, quarter = tid & 3;
        int r = row0 + rl;
        char* dh = sm + AH + rl * SKB + quarter * 64;   // 32 bf16 = 64 B per quarter
        char* dl = sm + AL + rl * SKB + quarter * 64;
        if (r < n) {
            const float4* A4 = (const float4*)(Ain + (size_t)r * NCH) + quarter * 8;
#pragma unroll
            for (int q = 0; q < 8; q++) {
                float4 v = A4[q];
                v.x = v.x >= 0.f ? v.x : av * v.x;
                v.y = v.y >= 0.f ? v.y : av * v.y;
                v.z = v.z >= 0.f ? v.z : av * v.z;
                v.w = v.w >= 0.f ? v.w : av * v.w;
                if (MODE == 0) {
                    float4 sc = ((const float4*)g_scale)[quarter * 8 + q];
                    float4 sf = ((const float4*)g_shift)[quarter * 8 + q];
                    v.x = fmaf(v.x, sc.x, sf.x); v.y = fmaf(v.y, sc.y, sf.y);
                    v.z = fmaf(v.z, sc.z, sf.z); v.w = fmaf(v.w, sc.w, sf.w);
                }
                __nv_bfloat16 hx = __float2bfloat16(v.x), hy = __float2bfloat16(v.y);
                __nv_bfloat16 hz = __float2bfloat16(v.z), hw = __float2bfloat16(v.w);
                uint2 hi; hi.x = pack_bf2(v.x, v.y); hi.y = pack_bf2(v.z, v.w);
                float lx = v.x - __bfloat162float(hx), ly = v.y - __bfloat162float(hy);
                float lz = v.z - __bfloat162float(hz), lw = v.w - __bfloat162float(hw);
                uint2 lo; lo.x = pack_bf2(lx, ly); lo.y = pack_bf2(lz, lw);
                *(uint2*)(dh + q * 8) = hi;
                *(uint2*)(dl + q * 8) = lo;
            }
        } else {
#pragma unroll
            for (int q = 0; q < 8; q++) {
                *(uint2*)(dh + q * 8) = make_uint2(0, 0);
                *(uint2*)(dl + q * 8) = make_uint2(0, 0);
            }
        }
    }
    // ---- W splits: 128 rows x 128 bf16, 2048 uint4 each ----
    {
        const uint4* wh4 = (const uint4*)Whi;
        const uint4* wl4 = (const uint4*)Wlo;
#pragma unroll
        for (int i = 0; i < 8; i++) {
            int idx = tid + i * 256;
            int rw = idx >> 4, cm = idx & 15;
            *(uint4*)(sm + WH + rw * SKB + cm * 16) = wh4[idx];
            *(uint4*)(sm + WL + rw * SKB + cm * 16) = wl4[idx];
        }
    }
    __syncthreads();

    int warp = tid >> 5, lane = tid & 31;
    int g = lane >> 2, tg = lane & 3;
    int m0 = (warp & 1) * 32;
    int n0 = (warp >> 1) * 32;
    int sel = lane >> 3, rowin = lane & 7;

    uint32_t sbase = (uint32_t)__cvta_generic_to_shared(sm);
    // A ldmatrix: regs {rows0-7/k0, rows8-15/k0, rows0-7/k8, rows8-15/k8}
    uint32_t aoffA = (uint32_t)((m0 + (sel & 1) * 8 + rowin) * SKB + (sel >> 1) * 16);
    // B ldmatrix: regs {n0-7/k0, n0-7/k8, n8-15/k0, n8-15/k8}
    uint32_t boffB = (uint32_t)((n0 + (sel >> 1) * 8 + rowin) * SKB + (sel & 1) * 16);

    float acc[2][4][4];
#pragma unroll
    for (int mt = 0; mt < 2; mt++)
#pragma unroll
        for (int j = 0; j < 4; j++)
#pragma unroll
            for (int v = 0; v < 4; v++) acc[mt][j][v] = 0.f;

#pragma unroll
    for (int kc = 0; kc < 8; kc++) {
        uint32_t kb = kc * 32;   // 16 bf16 = 32 bytes
        uint32_t ah[2][4], al[2][4];
#pragma unroll
        for (int mt = 0; mt < 2; mt++) {
            ldsm4(ah[mt], sbase + AH + aoffA + mt * (16 * SKB) + kb);
            ldsm4(al[mt], sbase + AL + aoffA + mt * (16 * SKB) + kb);
        }
#pragma unroll
        for (int jp = 0; jp < 2; jp++) {
            uint32_t bh[4], bl[4];
            ldsm4(bh, sbase + WH + boffB + jp * (16 * SKB) + kb);
            ldsm4(bl, sbase + WL + boffB + jp * (16 * SKB) + kb);
#pragma unroll
            for (int half = 0; half < 2; half++) {
                int j = jp * 2 + half;
#pragma unroll
                for (int mt = 0; mt < 2; mt++) {
                    mma16816(acc[mt][j], ah[mt], bh + half * 2);
                    mma16816(acc[mt][j], ah[mt], bl + half * 2);
                    mma16816(acc[mt][j], al[mt], bh + half * 2);
                }
            }
        }
    }

#pragma unroll
    for (int mt = 0; mt < 2; mt++) {
        int rA = row0 + m0 + mt * 16 + g;
        int rB = rA + 8;
#pragma unroll
        for (int j = 0; j < 4; j++) {
            int col = n0 + j * 8 + 2 * tg;
            if (rA < n)
                *(float2*)(g_h + (size_t)rA * NCH + col) = make_float2(acc[mt][j][0], acc[mt][j][1]);
            if (rB < n)
                *(float2*)(g_h + (size_t)rB * NCH + col) = make_float2(acc[mt][j][2], acc[mt][j][3]);
        }
    }
}

// ---------------- CSR gather (R4 form — unchanged) ----------------
__global__ void k_gather(const float* __restrict__ bvec, float* __restrict__ out, int n) {
    int warp = (blockIdx.x * blockDim.x + threadIdx.x) >> 5;
    int lane = threadIdx.x & 31;
    if (warp >= n) return;
    int off = g_rowptr[warp];
    int cnt = g_indeg[warp];
    float dr = g_dinv[warp];
    float inv = dr * dr;
    float4 hv = ((const float4*)(g_h + (size_t)warp * NCH))[lane];
    float4 bb = ((const float4*)bvec)[lane];
    float4 acc = make_float4(fmaf(hv.x, inv, bb.x), fmaf(hv.y, inv, bb.y),
                             fmaf(hv.z, inv, bb.z), fmaf(hv.w, inv, bb.w));
    for (int j = 0; j < cnt; j++) {
        int s = g_esrc[off + j];
        float c = g_dinv[s] * dr;
        float4 sv = ((const float4*)(g_h + (size_t)s * NCH))[lane];
        acc.x = fmaf(sv.x, c, acc.x);
        acc.y = fmaf(sv.y, c, acc.y);
        acc.z = fmaf(sv.z, c, acc.z);
        acc.w = fmaf(sv.w, c, acc.w);
    }
    ((float4*)(out + (size_t)warp * NCH))[lane] = acc;
}

// ---------------- launch ----------------
extern "C" void kernel_launch(void* const* d_in, const int* in_sizes, int n_in,
                              void* d_out, int out_size) {
    const float* x     = (const float*)d_in[0];
    const int*   ei    = (const int*)  d_in[1];
    const float* a1    = (const float*)d_in[2];
    const float* gamma = (const float*)d_in[3];
    const float* beta  = (const float*)d_in[4];
    const float* W1    = (const float*)d_in[5];
    const float* b1    = (const float*)d_in[6];
    const float* a2    = (const float*)d_in[7];
    const float* W2    = (const float*)d_in[8];
    const float* b2    = (const float*)d_in[9];
    float* out = (float*)d_out;

    int n = in_sizes[0] / NCH;
    int e = in_sizes[1] / 2;
    const int* src = ei;
    const int* dst = ei + e;

    const int SMEM = (2 * 64 + 2 * 128) * SKB;   // 104448 B
    cudaFuncSetAttribute(k_mma<0>, cudaFuncAttributeMaxDynamicSharedMemorySize, SMEM);
    cudaFuncSetAttribute(k_mma<1>, cudaFuncAttributeMaxDynamicSharedMemorySize, SMEM);

    float* accPtr = nullptr;
    cudaGetSymbolAddress((void**)&accPtr, g_acc);
    __nv_bfloat16* wtPtr = nullptr;
    cudaGetSymbolAddress((void**)&wtPtr, g_Wt);

    int mmaBlocks = (n + 63) / 64;
    int gatBlocks = (int)(((long long)n * 32 + 255) / 256);

    // 1-3: BN stats path
    k_convW<<<(NCH * NCH + 255) / 256, 256>>>(W1, W2);
    k_stats<<<1184, 256>>>(x, a1, n);
    k_finalize<<<1, 128>>>(gamma, beta, n);
    // 4: conv1 GEMM (ncu profile slot)
    k_mma<0><<<mmaBlocks, 256, SMEM>>>(x, wtPtr + 0 * NCH * NCH, wtPtr + 1 * NCH * NCH, a1, n);
    // CSR build
    k_zero<<<(n + 255) / 256, 256>>>(n);
    k_count<<<(e + 255) / 256, 256>>>(dst, e);
    k_scan1<<<NCHUNK, CHUNK>>>(n);
    k_scan2<<<1, CHUNK>>>();
    k_scan3<<<NCHUNK, CHUNK>>>(n);
    k_dinv<<<(n + 255) / 256, 256>>>(n);
    k_fill<<<(e + 255) / 256, 256>>>(src, dst, e);
    // conv1 aggregate
    k_gather<<<gatBlocks, 256>>>(b1, accPtr, n);
    // conv2
    k_mma<1><<<mmaBlocks, 256, SMEM>>>(accPtr, wtPtr + 2 * NCH * NCH, wtPtr + 3 * NCH * NCH, a2, n);
    k_gather<<<gatBlocks, 256>>>(b2, out, n);
}

// round 11
// speedup vs baseline: 1.0372x; 1.0372x over previous
#include <cuda_runtime.h>
#include <cuda_bf16.h>
#include <cstdint>

#define NNODES 200000
#define NEDGES 600000
#define NCH    128
#define SK     136            // padded bf16 row stride
#define SKB    (SK * 2)
#define CHUNK  512
#define NCHUNK ((NNODES + CHUNK - 1) / CHUNK)   // 391

// ---------------- scratch ----------------
__device__ float g_h[(size_t)NNODES * NCH];
__device__ float g_acc[(size_t)NNODES * NCH];
__device__ float g_dinv[NNODES];
__device__ int   g_indeg[NNODES];
__device__ int   g_cursor[NNODES];
__device__ int   g_rowptr[NNODES];
__device__ int   g_bsum[CHUNK];
__device__ int   g_bbase[CHUNK];
__device__ int   g_esrc[NEDGES];
__device__ float g_sum[NCH];
__device__ float g_sumsq[NCH];
__device__ float g_scale[NCH];
__device__ float g_shift[NCH];
__device__ __nv_bfloat16 g_Wt[4][NCH * NCH];   // W1hi W1lo W2hi W2lo, [n][k]

// ---------------- prep ----------------
__global__ void k_convW(const float* __restrict__ W1, const float* __restrict__ W2) {
    int idx = blockIdx.x * blockDim.x + threadIdx.x;
    if (idx < NCH) { g_sum[idx] = 0.f; g_sumsq[idx] = 0.f; }
    if (idx >= NCH * NCH) return;
    int nn = idx & 127, kk = idx >> 7;
    int o = nn * NCH + kk;
    float v1 = W1[idx], v2 = W2[idx];
    __nv_bfloat16 h1 = __float2bfloat16(v1);
    __nv_bfloat16 h2 = __float2bfloat16(v2);
    g_Wt[0][o] = h1; g_Wt[1][o] = __float2bfloat16(v1 - __bfloat162float(h1));
    g_Wt[2][o] = h2; g_Wt[3][o] = __float2bfloat16(v2 - __bfloat162float(h2));
}

__global__ void k_stats(const float* __restrict__ x, const float* __restrict__ aP, int n) {
    __shared__ float4 rs[8][32];
    __shared__ float4 rq[8][32];
    int tid = threadIdx.x, c4 = tid & 31, ry = tid >> 5;
    float av = aP[0];
    float4 s = make_float4(0, 0, 0, 0), q = make_float4(0, 0, 0, 0);
    for (int base = blockIdx.x * 32; base < n; base += gridDim.x * 32) {
#pragma unroll
        for (int u = 0; u < 4; u++) {
            int r = base + ry + u * 8;
            if (r < n) {
                float4 v = ((const float4*)x)[(size_t)r * 32 + c4];
                v.x = v.x >= 0.f ? v.x : av * v.x;
                v.y = v.y >= 0.f ? v.y : av * v.y;
                v.z = v.z >= 0.f ? v.z : av * v.z;
                v.w = v.w >= 0.f ? v.w : av * v.w;
                s.x += v.x; s.y += v.y; s.z += v.z; s.w += v.w;
                q.x += v.x * v.x; q.y += v.y * v.y; q.z += v.z * v.z; q.w += v.w * v.w;
            }
        }
    }
    rs[ry][c4] = s; rq[ry][c4] = q;
    __syncthreads();
    if (ry == 0) {
        float4 S = rs[0][c4], Q = rq[0][c4];
#pragma unroll
        for (int i = 1; i < 8; i++) {
            float4 a = rs[i][c4], b = rq[i][c4];
            S.x += a.x; S.y += a.y; S.z += a.z; S.w += a.w;
            Q.x += b.x; Q.y += b.y; Q.z += b.z; Q.w += b.w;
        }
        atomicAdd(&g_sum[c4 * 4 + 0], S.x); atomicAdd(&g_sum[c4 * 4 + 1], S.y);
        atomicAdd(&g_sum[c4 * 4 + 2], S.z); atomicAdd(&g_sum[c4 * 4 + 3], S.w);
        atomicAdd(&g_sumsq[c4 * 4 + 0], Q.x); atomicAdd(&g_sumsq[c4 * 4 + 1], Q.y);
        atomicAdd(&g_sumsq[c4 * 4 + 2], Q.z); atomicAdd(&g_sumsq[c4 * 4 + 3], Q.w);
    }
}

__global__ void k_finalize(const float* __restrict__ gamma, const float* __restrict__ beta, int n) {
    int c = threadIdx.x;
    if (c >= NCH) return;
    float invn = 1.0f / (float)n;
    float mean = g_sum[c] * invn;
    float var  = g_sumsq[c] * invn - mean * mean;
    float sc   = gamma[c] * rsqrtf(var + 1e-5f);
    g_scale[c] = sc;
    g_shift[c] = beta[c] - mean * sc;
}

__global__ void k_zero(int n) {
    int i = blockIdx.x * blockDim.x + threadIdx.x;
    if (i < n) { g_indeg[i] = 0; g_cursor[i] = 0; }
}
__global__ void k_count(const int* __restrict__ dst, int e) {
    int i = blockIdx.x * blockDim.x + threadIdx.x;
    if (i < e) atomicAdd(&g_indeg[dst[i]], 1);
}
__global__ void k_dinv(int n) {
    int i = blockIdx.x * blockDim.x + threadIdx.x;
    if (i < n) g_dinv[i] = rsqrtf((float)(g_indeg[i] + 1));
}

__global__ void k_scan1(int n) {
    __shared__ int sh[CHUNK];
    int i = blockIdx.x * CHUNK + threadIdx.x;
    sh[threadIdx.x] = (i < n) ? g_indeg[i] : 0;
    __syncthreads();
    for (int s = CHUNK / 2; s > 0; s >>= 1) {
        if (threadIdx.x < s) sh[threadIdx.x] += sh[threadIdx.x + s];
        __syncthreads();
    }
    if (threadIdx.x == 0) g_bsum[blockIdx.x] = sh[0];
}
__global__ void k_scan2() {
    __shared__ int sh[CHUNK];
    int t = threadIdx.x;
    sh[t] = (t < NCHUNK) ? g_bsum[t] : 0;
    __syncthreads();
    for (int d = 1; d < CHUNK; d <<= 1) {
        int v = (t >= d) ? sh[t - d] : 0;
        __syncthreads();
        sh[t] += v;
        __syncthreads();
    }
    if (t < NCHUNK) g_bbase[t] = (t == 0) ? 0 : sh[t - 1];
}
__global__ void k_scan3(int n) {
    __shared__ int sh[CHUNK];
    int t = threadIdx.x;
    int i = blockIdx.x * CHUNK + t;
    int v0 = (i < n) ? g_indeg[i] : 0;
    sh[t] = v0;
    __syncthreads();
    for (int d = 1; d < CHUNK; d <<= 1) {
        int v = (t >= d) ? sh[t - d] : 0;
        __syncthreads();
        sh[t] += v;
        __syncthreads();
    }
    if (i < n) g_rowptr[i] = g_bbase[blockIdx.x] + sh[t] - v0;
}
__global__ void k_fill(const int* __restrict__ src, const int* __restrict__ dst, int e) {
    int i = blockIdx.x * blockDim.x + threadIdx.x;
    if (i >= e) return;
    int d = dst[i];
    int pos = g_rowptr[d] + atomicAdd(&g_cursor[d], 1);
    g_esrc[pos] = src[i];
}

// ---------------- HMMA helpers ----------------
__device__ __forceinline__ void mma16816(float* c, const uint32_t* a, const uint32_t* b) {
    asm volatile(
        "mma.sync.aligned.m16n8k16.row.col.f32.bf16.bf16.f32 "
        "{%0,%1,%2,%3}, {%4,%5,%6,%7}, {%8,%9}, {%0,%1,%2,%3};"
        : "+f"(c[0]), "+f"(c[1]), "+f"(c[2]), "+f"(c[3])
        : "r"(a[0]), "r"(a[1]), "r"(a[2]), "r"(a[3]), "r"(b[0]), "r"(b[1]));
}
__device__ __forceinline__ void ldsm4(uint32_t* r, uint32_t addr) {
    asm volatile("ldmatrix.sync.aligned.m8n8.x4.shared.b16 {%0,%1,%2,%3}, [%4];"
                 : "=r"(r[0]), "=r"(r[1]), "=r"(r[2]), "=r"(r[3]) : "r"(addr));
}
__device__ __forceinline__ uint32_t pack_bf2(float x, float y) {
    __nv_bfloat162 h = __floats2bfloat162_rn(x, y);
    return *(uint32_t*)&h;
}

// ---------------- GEMM: g_h = f(A) @ W  (R9 config: M-tile 128, ldmatrix) ----------------
template <int MODE>
__global__ void __launch_bounds__(256)
k_mma(const float* __restrict__ Ain,
      const __nv_bfloat16* __restrict__ Whi, const __nv_bfloat16* __restrict__ Wlo,
      const float* __restrict__ aP, int n)
{
    extern __shared__ char sm[];
    const int AH = 0, AL = 128 * SKB, WH = 2 * 128 * SKB, WL = 3 * 128 * SKB;
    int tid = threadIdx.x;
    float av = aP[0];
    int row0 = blockIdx.x * 128;

    // ---- A tile: load, transform, hi/lo split ----
    {
        int rl = tid >> 1, half = tid & 1;
        int r = row0 + rl;
        char* dh = sm + AH + rl * SKB + half * 128;
        char* dl = sm + AL + rl * SKB + half * 128;
        if (r < n) {
            const float4* A4 = (const float4*)(Ain + (size_t)r * NCH) + half * 16;
#pragma unroll
            for (int q = 0; q < 16; q++) {
                float4 v = A4[q];
                v.x = v.x >= 0.f ? v.x : av * v.x;
                v.y = v.y >= 0.f ? v.y : av * v.y;
                v.z = v.z >= 0.f ? v.z : av * v.z;
                v.w = v.w >= 0.f ? v.w : av * v.w;
                if (MODE == 0) {
                    float4 sc = ((const float4*)g_scale)[half * 16 + q];
                    float4 sf = ((const float4*)g_shift)[half * 16 + q];
                    v.x = fmaf(v.x, sc.x, sf.x); v.y = fmaf(v.y, sc.y, sf.y);
                    v.z = fmaf(v.z, sc.z, sf.z); v.w = fmaf(v.w, sc.w, sf.w);
                }
                __nv_bfloat16 hx = __float2bfloat16(v.x), hy = __float2bfloat16(v.y);
                __nv_bfloat16 hz = __float2bfloat16(v.z), hw = __float2bfloat16(v.w);
                uint2 hi; hi.x = pack_bf2(v.x, v.y); hi.y = pack_bf2(v.z, v.w);
                float lx = v.x - __bfloat162float(hx), ly = v.y - __bfloat162float(hy);
                float lz = v.z - __bfloat162float(hz), lw = v.w - __bfloat162float(hw);
                uint2 lo; lo.x = pack_bf2(lx, ly); lo.y = pack_bf2(lz, lw);
                *(uint2*)(dh + q * 8) = hi;
                *(uint2*)(dl + q * 8) = lo;
            }
        } else {
#pragma unroll
            for (int q = 0; q < 16; q++) {
                *(uint2*)(dh + q * 8) = make_uint2(0, 0);
                *(uint2*)(dl + q * 8) = make_uint2(0, 0);
            }
        }
    }
    // ---- W splits ----
    {
        const uint4* wh4 = (const uint4*)Whi;
        const uint4* wl4 = (const uint4*)Wlo;
#pragma unroll
        for (int i = 0; i < 8; i++) {
            int idx = tid + i * 256;
            int rw = idx >> 4, cm = idx & 15;
            *(uint4*)(sm + WH + rw * SKB + cm * 16) = wh4[idx];
            *(uint4*)(sm + WL + rw * SKB + cm * 16) = wl4[idx];
        }
    }
    __syncthreads();

    int warp = tid >> 5, lane = tid & 31;
    int g = lane >> 2, tg = lane & 3;
    int m0 = (warp & 3) * 32;
    int n0 = (warp >> 2) * 64;
    int sel = lane >> 3, rowin = lane & 7;

    uint32_t sbase = (uint32_t)__cvta_generic_to_shared(sm);
    uint32_t aoffA = (uint32_t)((m0 + (sel & 1) * 8 + rowin) * SKB + (sel >> 1) * 16);
    uint32_t boffB = (uint32_t)((n0 + (sel >> 1) * 8 + rowin) * SKB + (sel & 1) * 16);

    float acc[2][8][4];
#pragma unroll
    for (int mt = 0; mt < 2; mt++)
#pragma unroll
        for (int j = 0; j < 8; j++)
#pragma unroll
            for (int v = 0; v < 4; v++) acc[mt][j][v] = 0.f;

#pragma unroll
    for (int kc = 0; kc < 8; kc++) {
        uint32_t kb = kc * 32;
        uint32_t ah[2][4], al[2][4];
#pragma unroll
        for (int mt = 0; mt < 2; mt++) {
            ldsm4(ah[mt], sbase + AH + aoffA + mt * (16 * SKB) + kb);
            ldsm4(al[mt], sbase + AL + aoffA + mt * (16 * SKB) + kb);
        }
#pragma unroll
        for (int jp = 0; jp < 4; jp++) {
            uint32_t bh[4], bl[4];
            ldsm4(bh, sbase + WH + boffB + jp * (16 * SKB) + kb);
            ldsm4(bl, sbase + WL + boffB + jp * (16 * SKB) + kb);
#pragma unroll
            for (int half = 0; half < 2; half++) {
                int j = jp * 2 + half;
#pragma unroll
                for (int mt = 0; mt < 2; mt++) {
                    mma16816(acc[mt][j], ah[mt], bh + half * 2);
                    mma16816(acc[mt][j], ah[mt], bl + half * 2);
                    mma16816(acc[mt][j], al[mt], bh + half * 2);
                }
            }
        }
    }

#pragma unroll
    for (int mt = 0; mt < 2; mt++) {
        int rA = row0 + m0 + mt * 16 + g;
        int rB = rA + 8;
#pragma unroll
        for (int j = 0; j < 8; j++) {
            int col = n0 + j * 8 + 2 * tg;
            if (rA < n)
                *(float2*)(g_h + (size_t)rA * NCH + col) = make_float2(acc[mt][j][0], acc[mt][j][1]);
            if (rB < n)
                *(float2*)(g_h + (size_t)rB * NCH + col) = make_float2(acc[mt][j][2], acc[mt][j][3]);
        }
    }
}

// ---------------- CSR gather: 2-way software-pipelined ----------------
// out[d] = h[d]/deg + b + sum_{s in N(d)} dinv[s]*dinv[d]*h[s]
__global__ void k_gather(const float* __restrict__ bvec, float* __restrict__ out, int n) {
    int node = (blockIdx.x * blockDim.x + threadIdx.x) >> 5;
    int lane = threadIdx.x & 31;
    if (node >= n) return;
    int off = g_rowptr[node];
    int cnt = g_indeg[node];
    float dr = g_dinv[node];
    float inv = dr * dr;
    float4 hv = ((const float4*)(g_h + (size_t)node * NCH))[lane];
    float4 bb = ((const float4*)bvec)[lane];
    float4 acc = make_float4(fmaf(hv.x, inv, bb.x), fmaf(hv.y, inv, bb.y),
                             fmaf(hv.z, inv, bb.z), fmaf(hv.w, inv, bb.w));
    int j = 0;
    for (; j + 2 <= cnt; j += 2) {
        int sa = __ldg(g_esrc + off + j);
        int sb = __ldg(g_esrc + off + j + 1);
        float ca = __ldg(g_dinv + sa) * dr;
        float cb = __ldg(g_dinv + sb) * dr;
        float4 va = __ldg(((const float4*)(g_h + (size_t)sa * NCH)) + lane);
        float4 vb = __ldg(((const float4*)(g_h + (size_t)sb * NCH)) + lane);
        acc.x = fmaf(va.x, ca, acc.x); acc.y = fmaf(va.y, ca, acc.y);
        acc.z = fmaf(va.z, ca, acc.z); acc.w = fmaf(va.w, ca, acc.w);
        acc.x = fmaf(vb.x, cb, acc.x); acc.y = fmaf(vb.y, cb, acc.y);
        acc.z = fmaf(vb.z, cb, acc.z); acc.w = fmaf(vb.w, cb, acc.w);
    }
    if (j < cnt) {
        int s = __ldg(g_esrc + off + j);
        float c = __ldg(g_dinv + s) * dr;
        float4 sv = __ldg(((const float4*)(g_h + (size_t)s * NCH)) + lane);
        acc.x = fmaf(sv.x, c, acc.x); acc.y = fmaf(sv.y, c, acc.y);
        acc.z = fmaf(sv.z, c, acc.z); acc.w = fmaf(sv.w, c, acc.w);
    }
    ((float4*)(out + (size_t)node * NCH))[lane] = acc;
}

// ---------------- launch ----------------
extern "C" void kernel_launch(void* const* d_in, const int* in_sizes, int n_in,
                              void* d_out, int out_size) {
    const float* x     = (const float*)d_in[0];
    const int*   ei    = (const int*)  d_in[1];
    const float* a1    = (const float*)d_in[2];
    const float* gamma = (const float*)d_in[3];
    const float* beta  = (const float*)d_in[4];
    const float* W1    = (const float*)d_in[5];
    const float* b1    = (const float*)d_in[6];
    const float* a2    = (const float*)d_in[7];
    const float* W2    = (const float*)d_in[8];
    const float* b2    = (const float*)d_in[9];
    float* out = (float*)d_out;

    int n = in_sizes[0] / NCH;
    int e = in_sizes[1] / 2;
    const int* src = ei;
    const int* dst = ei + e;

    const int SMEM = 4 * 128 * SKB;   // 139264 B
    cudaFuncSetAttribute(k_mma<0>, cudaFuncAttributeMaxDynamicSharedMemorySize, SMEM);
    cudaFuncSetAttribute(k_mma<1>, cudaFuncAttributeMaxDynamicSharedMemorySize, SMEM);

    float* accPtr = nullptr;
    cudaGetSymbolAddress((void**)&accPtr, g_acc);
    __nv_bfloat16* wtPtr = nullptr;
    cudaGetSymbolAddress((void**)&wtPtr, g_Wt);

    int mmaBlocks = (n + 127) / 128;
    int gatBlocks = (int)(((long long)n * 32 + 255) / 256);

    // 1-3: BN stats path
    k_convW<<<(NCH * NCH + 255) / 256, 256>>>(W1, W2);
    k_stats<<<1184, 256>>>(x, a1, n);
    k_finalize<<<1, 128>>>(gamma, beta, n);
    // 4: conv1 GEMM (ncu profile slot)
    k_mma<0><<<mmaBlocks, 256, SMEM>>>(x, wtPtr + 0 * NCH * NCH, wtPtr + 1 * NCH * NCH, a1, n);
    // CSR build
    k_zero<<<(n + 255) / 256, 256>>>(n);
    k_count<<<(e + 255) / 256, 256>>>(dst, e);
    k_scan1<<<NCHUNK, CHUNK>>>(n);
    k_scan2<<<1, CHUNK>>>();
    k_scan3<<<NCHUNK, CHUNK>>>(n);
    k_dinv<<<(n + 255) / 256, 256>>>(n);
    k_fill<<<(e + 255) / 256, 256>>>(src, dst, e);
    // conv1 aggregate
    k_gather<<<gatBlocks, 256>>>(b1, accPtr, n);
    // conv2
    k_mma<1><<<mmaBlocks, 256, SMEM>>>(accPtr, wtPtr + 2 * NCH * NCH, wtPtr + 3 * NCH * NCH, a2, n);
    k_gather<<<gatBlocks, 256>>>(b2, out, n);
}

// round 12
// speedup vs baseline: 1.0613x; 1.0232x over previous
#include <cuda_runtime.h>
#include <cuda_bf16.h>
#include <cstdint>

#define NNODES 200000
#define NEDGES 600000
#define NCH    128
#define SK     136            // padded bf16 row stride
#define SKB    (SK * 2)
#define CHUNK  512
#define NCHUNK ((NNODES + CHUNK - 1) / CHUNK)   // 391
#define MMA_GRID 296

// ---------------- scratch ----------------
__device__ float g_h[(size_t)NNODES * NCH];
__device__ float g_acc[(size_t)NNODES * NCH];
__device__ float g_dinv[NNODES];
__device__ int   g_indeg[NNODES];
__device__ int   g_cursor[NNODES];
__device__ int   g_rowptr[NNODES];
__device__ int   g_bsum[CHUNK];
__device__ int   g_bbase[CHUNK];
__device__ int   g_esrc[NEDGES];
__device__ float g_sum[NCH];
__device__ float g_sumsq[NCH];
__device__ float g_scale[NCH];
__device__ float g_shift[NCH];
__device__ __nv_bfloat16 g_Wt[4][NCH * NCH];   // W1hi W1lo W2hi W2lo, [n][k]

// ---------------- prep ----------------
__global__ void k_convW(const float* __restrict__ W1, const float* __restrict__ W2) {
    int idx = blockIdx.x * blockDim.x + threadIdx.x;
    if (idx < NCH) { g_sum[idx] = 0.f; g_sumsq[idx] = 0.f; }
    if (idx >= NCH * NCH) return;
    int nn = idx & 127, kk = idx >> 7;
    int o = nn * NCH + kk;
    float v1 = W1[idx], v2 = W2[idx];
    __nv_bfloat16 h1 = __float2bfloat16(v1);
    __nv_bfloat16 h2 = __float2bfloat16(v2);
    g_Wt[0][o] = h1; g_Wt[1][o] = __float2bfloat16(v1 - __bfloat162float(h1));
    g_Wt[2][o] = h2; g_Wt[3][o] = __float2bfloat16(v2 - __bfloat162float(h2));
}

__global__ void k_stats(const float* __restrict__ x, const float* __restrict__ aP, int n) {
    __shared__ float4 rs[8][32];
    __shared__ float4 rq[8][32];
    int tid = threadIdx.x, c4 = tid & 31, ry = tid >> 5;
    float av = aP[0];
    float4 s = make_float4(0, 0, 0, 0), q = make_float4(0, 0, 0, 0);
    for (int base = blockIdx.x * 32; base < n; base += gridDim.x * 32) {
#pragma unroll
        for (int u = 0; u < 4; u++) {
            int r = base + ry + u * 8;
            if (r < n) {
                float4 v = ((const float4*)x)[(size_t)r * 32 + c4];
                v.x = v.x >= 0.f ? v.x : av * v.x;
                v.y = v.y >= 0.f ? v.y : av * v.y;
                v.z = v.z >= 0.f ? v.z : av * v.z;
                v.w = v.w >= 0.f ? v.w : av * v.w;
                s.x += v.x; s.y += v.y; s.z += v.z; s.w += v.w;
                q.x += v.x * v.x; q.y += v.y * v.y; q.z += v.z * v.z; q.w += v.w * v.w;
            }
        }
    }
    rs[ry][c4] = s; rq[ry][c4] = q;
    __syncthreads();
    if (ry == 0) {
        float4 S = rs[0][c4], Q = rq[0][c4];
#pragma unroll
        for (int i = 1; i < 8; i++) {
            float4 a = rs[i][c4], b = rq[i][c4];
            S.x += a.x; S.y += a.y; S.z += a.z; S.w += a.w;
            Q.x += b.x; Q.y += b.y; Q.z += b.z; Q.w += b.w;
        }
        atomicAdd(&g_sum[c4 * 4 + 0], S.x); atomicAdd(&g_sum[c4 * 4 + 1], S.y);
        atomicAdd(&g_sum[c4 * 4 + 2], S.z); atomicAdd(&g_sum[c4 * 4 + 3], S.w);
        atomicAdd(&g_sumsq[c4 * 4 + 0], Q.x); atomicAdd(&g_sumsq[c4 * 4 + 1], Q.y);
        atomicAdd(&g_sumsq[c4 * 4 + 2], Q.z); atomicAdd(&g_sumsq[c4 * 4 + 3], Q.w);
    }
}

__global__ void k_finalize(const float* __restrict__ gamma, const float* __restrict__ beta, int n) {
    int c = threadIdx.x;
    if (c >= NCH) return;
    float invn = 1.0f / (float)n;
    float mean = g_sum[c] * invn;
    float var  = g_sumsq[c] * invn - mean * mean;
    float sc   = gamma[c] * rsqrtf(var + 1e-5f);
    g_scale[c] = sc;
    g_shift[c] = beta[c] - mean * sc;
}

__global__ void k_zero(int n) {
    int i = blockIdx.x * blockDim.x + threadIdx.x;
    if (i < n) { g_indeg[i] = 0; g_cursor[i] = 0; }
}
__global__ void k_count(const int* __restrict__ dst, int e) {
    int i = blockIdx.x * blockDim.x + threadIdx.x;
    if (i < e) atomicAdd(&g_indeg[dst[i]], 1);
}
__global__ void k_dinv(int n) {
    int i = blockIdx.x * blockDim.x + threadIdx.x;
    if (i < n) g_dinv[i] = rsqrtf((float)(g_indeg[i] + 1));
}

__global__ void k_scan1(int n) {
    __shared__ int sh[CHUNK];
    int i = blockIdx.x * CHUNK + threadIdx.x;
    sh[threadIdx.x] = (i < n) ? g_indeg[i] : 0;
    __syncthreads();
    for (int s = CHUNK / 2; s > 0; s >>= 1) {
        if (threadIdx.x < s) sh[threadIdx.x] += sh[threadIdx.x + s];
        __syncthreads();
    }
    if (threadIdx.x == 0) g_bsum[blockIdx.x] = sh[0];
}
__global__ void k_scan2() {
    __shared__ int sh[CHUNK];
    int t = threadIdx.x;
    sh[t] = (t < NCHUNK) ? g_bsum[t] : 0;
    __syncthreads();
    for (int d = 1; d < CHUNK; d <<= 1) {
        int v = (t >= d) ? sh[t - d] : 0;
        __syncthreads();
        sh[t] += v;
        __syncthreads();
    }
    if (t < NCHUNK) g_bbase[t] = (t == 0) ? 0 : sh[t - 1];
}
__global__ void k_scan3(int n) {
    __shared__ int sh[CHUNK];
    int t = threadIdx.x;
    int i = blockIdx.x * CHUNK + t;
    int v0 = (i < n) ? g_indeg[i] : 0;
    sh[t] = v0;
    __syncthreads();
    for (int d = 1; d < CHUNK; d <<= 1) {
        int v = (t >= d) ? sh[t - d] : 0;
        __syncthreads();
        sh[t] += v;
        __syncthreads();
    }
    if (i < n) g_rowptr[i] = g_bbase[blockIdx.x] + sh[t] - v0;
}
__global__ void k_fill(const int* __restrict__ src, const int* __restrict__ dst, int e) {
    int i = blockIdx.x * blockDim.x + threadIdx.x;
    if (i >= e) return;
    int d = dst[i];
    int pos = g_rowptr[d] + atomicAdd(&g_cursor[d], 1);
    g_esrc[pos] = src[i];
}

// ---------------- HMMA helpers ----------------
__device__ __forceinline__ void mma16816(float* c, const uint32_t* a, const uint32_t* b) {
    asm volatile(
        "mma.sync.aligned.m16n8k16.row.col.f32.bf16.bf16.f32 "
        "{%0,%1,%2,%3}, {%4,%5,%6,%7}, {%8,%9}, {%0,%1,%2,%3};"
        : "+f"(c[0]), "+f"(c[1]), "+f"(c[2]), "+f"(c[3])
        : "r"(a[0]), "r"(a[1]), "r"(a[2]), "r"(a[3]), "r"(b[0]), "r"(b[1]));
}
__device__ __forceinline__ void ldsm4(uint32_t* r, uint32_t addr) {
    asm volatile("ldmatrix.sync.aligned.m8n8.x4.shared.b16 {%0,%1,%2,%3}, [%4];"
                 : "=r"(r[0]), "=r"(r[1]), "=r"(r[2]), "=r"(r[3]) : "r"(addr));
}
__device__ __forceinline__ uint32_t pack_bf2(float x, float y) {
    __nv_bfloat162 h = __floats2bfloat162_rn(x, y);
    return *(uint32_t*)&h;
}

// ---------------- persistent GEMM: g_h = f(A) @ W ----------------
// W loaded to smem ONCE per CTA; CTA loops over 128-row tiles with stride gridDim.x.
template <int MODE>
__global__ void __launch_bounds__(256)
k_mma(const float* __restrict__ Ain,
      const __nv_bfloat16* __restrict__ Whi, const __nv_bfloat16* __restrict__ Wlo,
      const float* __restrict__ aP, int n, int ntiles)
{
    extern __shared__ char sm[];
    const int AH = 0, AL = 128 * SKB, WH = 2 * 128 * SKB, WL = 3 * 128 * SKB;
    int tid = threadIdx.x;
    float av = aP[0];

    // ---- W splits: once per CTA ----
    {
        const uint4* wh4 = (const uint4*)Whi;
        const uint4* wl4 = (const uint4*)Wlo;
#pragma unroll
        for (int i = 0; i < 8; i++) {
            int idx = tid + i * 256;
            int rw = idx >> 4, cm = idx & 15;
            *(uint4*)(sm + WH + rw * SKB + cm * 16) = wh4[idx];
            *(uint4*)(sm + WL + rw * SKB + cm * 16) = wl4[idx];
        }
    }

    int warp = tid >> 5, lane = tid & 31;
    int g = lane >> 2, tg = lane & 3;
    int m0 = (warp & 3) * 32;
    int n0 = (warp >> 2) * 64;
    int sel = lane >> 3, rowin = lane & 7;

    uint32_t sbase = (uint32_t)__cvta_generic_to_shared(sm);
    uint32_t aoffA = (uint32_t)((m0 + (sel & 1) * 8 + rowin) * SKB + (sel >> 1) * 16);
    uint32_t boffB = (uint32_t)((n0 + (sel >> 1) * 8 + rowin) * SKB + (sel & 1) * 16);

    int rl = tid >> 1, half = tid & 1;

    for (int t = blockIdx.x; t < ntiles; t += gridDim.x) {
        int row0 = t * 128;

        // ---- A tile: load, transform, hi/lo split ----
        {
            int r = row0 + rl;
            char* dh = sm + AH + rl * SKB + half * 128;
            char* dl = sm + AL + rl * SKB + half * 128;
            if (r < n) {
                const float4* A4 = (const float4*)(Ain + (size_t)r * NCH) + half * 16;
#pragma unroll
                for (int q = 0; q < 16; q++) {
                    float4 v = A4[q];
                    v.x = v.x >= 0.f ? v.x : av * v.x;
                    v.y = v.y >= 0.f ? v.y : av * v.y;
                    v.z = v.z >= 0.f ? v.z : av * v.z;
                    v.w = v.w >= 0.f ? v.w : av * v.w;
                    if (MODE == 0) {
                        float4 sc = ((const float4*)g_scale)[half * 16 + q];
                        float4 sf = ((const float4*)g_shift)[half * 16 + q];
                        v.x = fmaf(v.x, sc.x, sf.x); v.y = fmaf(v.y, sc.y, sf.y);
                        v.z = fmaf(v.z, sc.z, sf.z); v.w = fmaf(v.w, sc.w, sf.w);
                    }
                    __nv_bfloat16 hx = __float2bfloat16(v.x), hy = __float2bfloat16(v.y);
                    __nv_bfloat16 hz = __float2bfloat16(v.z), hw = __float2bfloat16(v.w);
                    uint2 hi; hi.x = pack_bf2(v.x, v.y); hi.y = pack_bf2(v.z, v.w);
                    float lx = v.x - __bfloat162float(hx), ly = v.y - __bfloat162float(hy);
                    float lz = v.z - __bfloat162float(hz), lw = v.w - __bfloat162float(hw);
                    uint2 lo; lo.x = pack_bf2(lx, ly); lo.y = pack_bf2(lz, lw);
                    *(uint2*)(dh + q * 8) = hi;
                    *(uint2*)(dl + q * 8) = lo;
                }
            } else {
#pragma unroll
                for (int q = 0; q < 16; q++) {
                    *(uint2*)(dh + q * 8) = make_uint2(0, 0);
                    *(uint2*)(dl + q * 8) = make_uint2(0, 0);
                }
            }
        }
        __syncthreads();

        float acc[2][8][4];
#pragma unroll
        for (int mt = 0; mt < 2; mt++)
#pragma unroll
            for (int j = 0; j < 8; j++)
#pragma unroll
                for (int v = 0; v < 4; v++) acc[mt][j][v] = 0.f;

#pragma unroll
        for (int kc = 0; kc < 8; kc++) {
            uint32_t kb = kc * 32;
            uint32_t ah[2][4], al[2][4];
#pragma unroll
            for (int mt = 0; mt < 2; mt++) {
                ldsm4(ah[mt], sbase + AH + aoffA + mt * (16 * SKB) + kb);
                ldsm4(al[mt], sbase + AL + aoffA + mt * (16 * SKB) + kb);
            }
#pragma unroll
            for (int jp = 0; jp < 4; jp++) {
                uint32_t bh[4], bl[4];
                ldsm4(bh, sbase + WH + boffB + jp * (16 * SKB) + kb);
                ldsm4(bl, sbase + WL + boffB + jp * (16 * SKB) + kb);
#pragma unroll
                for (int hf = 0; hf < 2; hf++) {
                    int j = jp * 2 + hf;
#pragma unroll
                    for (int mt = 0; mt < 2; mt++) {
                        mma16816(acc[mt][j], ah[mt], bh + hf * 2);
                        mma16816(acc[mt][j], ah[mt], bl + hf * 2);
                        mma16816(acc[mt][j], al[mt], bh + hf * 2);
                    }
                }
            }
        }

#pragma unroll
        for (int mt = 0; mt < 2; mt++) {
            int rA = row0 + m0 + mt * 16 + g;
            int rB = rA + 8;
#pragma unroll
            for (int j = 0; j < 8; j++) {
                int col = n0 + j * 8 + 2 * tg;
                if (rA < n)
                    *(float2*)(g_h + (size_t)rA * NCH + col) = make_float2(acc[mt][j][0], acc[mt][j][1]);
                if (rB < n)
                    *(float2*)(g_h + (size_t)rB * NCH + col) = make_float2(acc[mt][j][2], acc[mt][j][3]);
            }
        }
        __syncthreads();   // protect A smem before next tile's fill
    }
}

// ---------------- CSR gather: 2-way software-pipelined ----------------
__global__ void k_gather(const float* __restrict__ bvec, float* __restrict__ out, int n) {
    int node = (blockIdx.x * blockDim.x + threadIdx.x) >> 5;
    int lane = threadIdx.x & 31;
    if (node >= n) return;
    int off = g_rowptr[node];
    int cnt = g_indeg[node];
    float dr = g_dinv[node];
    float inv = dr * dr;
    float4 hv = ((const float4*)(g_h + (size_t)node * NCH))[lane];
    float4 bb = ((const float4*)bvec)[lane];
    float4 acc = make_float4(fmaf(hv.x, inv, bb.x), fmaf(hv.y, inv, bb.y),
                             fmaf(hv.z, inv, bb.z), fmaf(hv.w, inv, bb.w));
    int j = 0;
    for (; j + 2 <= cnt; j += 2) {
        int sa = __ldg(g_esrc + off + j);
        int sb = __ldg(g_esrc + off + j + 1);
        float ca = __ldg(g_dinv + sa) * dr;
        float cb = __ldg(g_dinv + sb) * dr;
        float4 va = __ldg(((const float4*)(g_h + (size_t)sa * NCH)) + lane);
        float4 vb = __ldg(((const float4*)(g_h + (size_t)sb * NCH)) + lane);
        acc.x = fmaf(va.x, ca, acc.x); acc.y = fmaf(va.y, ca, acc.y);
        acc.z = fmaf(va.z, ca, acc.z); acc.w = fmaf(va.w, ca, acc.w);
        acc.x = fmaf(vb.x, cb, acc.x); acc.y = fmaf(vb.y, cb, acc.y);
        acc.z = fmaf(vb.z, cb, acc.z); acc.w = fmaf(vb.w, cb, acc.w);
    }
    if (j < cnt) {
        int s = __ldg(g_esrc + off + j);
        float c = __ldg(g_dinv + s) * dr;
        float4 sv = __ldg(((const float4*)(g_h + (size_t)s * NCH)) + lane);
        acc.x = fmaf(sv.x, c, acc.x); acc.y = fmaf(sv.y, c, acc.y);
        acc.z = fmaf(sv.z, c, acc.z); acc.w = fmaf(sv.w, c, acc.w);
    }
    ((float4*)(out + (size_t)node * NCH))[lane] = acc;
}

// ---------------- launch ----------------
extern "C" void kernel_launch(void* const* d_in, const int* in_sizes, int n_in,
                              void* d_out, int out_size) {
    const float* x     = (const float*)d_in[0];
    const int*   ei    = (const int*)  d_in[1];
    const float* a1    = (const float*)d_in[2];
    const float* gamma = (const float*)d_in[3];
    const float* beta  = (const float*)d_in[4];
    const float* W1    = (const float*)d_in[5];
    const float* b1    = (const float*)d_in[6];
    const float* a2    = (const float*)d_in[7];
    const float* W2    = (const float*)d_in[8];
    const float* b2    = (const float*)d_in[9];
    float* out = (float*)d_out;

    int n = in_sizes[0] / NCH;
    int e = in_sizes[1] / 2;
    const int* src = ei;
    const int* dst = ei + e;

    const int SMEM = 4 * 128 * SKB;   // 139264 B
    cudaFuncSetAttribute(k_mma<0>, cudaFuncAttributeMaxDynamicSharedMemorySize, SMEM);
    cudaFuncSetAttribute(k_mma<1>, cudaFuncAttributeMaxDynamicSharedMemorySize, SMEM);

    float* accPtr = nullptr;
    cudaGetSymbolAddress((void**)&accPtr, g_acc);
    __nv_bfloat16* wtPtr = nullptr;
    cudaGetSymbolAddress((void**)&wtPtr, g_Wt);

    int ntiles = (n + 127) / 128;
    int gatBlocks = (int)(((long long)n * 32 + 255) / 256);

    // 1-3: BN stats path
    k_convW<<<(NCH * NCH + 255) / 256, 256>>>(W1, W2);
    k_stats<<<1184, 256>>>(x, a1, n);
    k_finalize<<<1, 128>>>(gamma, beta, n);
    // 4: conv1 GEMM (ncu profile slot), persistent
    k_mma<0><<<MMA_GRID, 256, SMEM>>>(x, wtPtr + 0 * NCH * NCH, wtPtr + 1 * NCH * NCH, a1, n, ntiles);
    // CSR build
    k_zero<<<(n + 255) / 256, 256>>>(n);
    k_count<<<(e + 255) / 256, 256>>>(dst, e);
    k_scan1<<<NCHUNK, CHUNK>>>(n);
    k_scan2<<<1, CHUNK>>>();
    k_scan3<<<NCHUNK, CHUNK>>>(n);
    k_dinv<<<(n + 255) / 256, 256>>>(n);
    k_fill<<<(e + 255) / 256, 256>>>(src, dst, e);
    // conv1 aggregate
    k_gather<<<gatBlocks, 256>>>(b1, accPtr, n);
    // conv2
    k_mma<1><<<MMA_GRID, 256, SMEM>>>(accPtr, wtPtr + 2 * NCH * NCH, wtPtr + 3 * NCH * NCH, a2, n, ntiles);
    k_gather<<<gatBlocks, 256>>>(b2, out, n);
}

// round 14
// speedup vs baseline: 1.1886x; 1.1199x over previous
#include <cuda_runtime.h>
#include <cuda_bf16.h>
#include <cstdint>

#define NNODES 200000
#define NEDGES 600000
#define NCH    128
#define SK     136            // padded bf16 row stride
#define SKB    (SK * 2)
#define CHUNK  512
#define NCHUNK ((NNODES + CHUNK - 1) / CHUNK)   // 391
#define MMA_GRID 148
#define STG_STRIDE 528        // staged f32 row stride (16B-aligned, low-conflict)

// ---------------- scratch ----------------
__device__ float g_h[(size_t)NNODES * NCH];
__device__ float g_acc[(size_t)NNODES * NCH];
__device__ float g_dinv[NNODES];
__device__ int   g_indeg[NNODES];
__device__ int   g_cursor[NNODES];
__device__ int   g_rowptr[NNODES];
__device__ int   g_bsum[CHUNK];
__device__ int   g_bbase[CHUNK];
__device__ int   g_esrc[NEDGES];
__device__ float g_sum[NCH];
__device__ float g_sumsq[NCH];
__device__ float g_scale[NCH];
__device__ float g_shift[NCH];
__device__ __nv_bfloat16 g_Wt[4][NCH * NCH];   // W1hi W1lo W2hi W2lo, [n][k]

// ---------------- prep ----------------
// transpose + hi/lo split W; zero BN accumulators + CSR counters
__global__ void k_convW(const float* __restrict__ W1, const float* __restrict__ W2, int n) {
    int idx = blockIdx.x * blockDim.x + threadIdx.x;
    if (idx < NCH) { g_sum[idx] = 0.f; g_sumsq[idx] = 0.f; }
    if (idx < n) { g_indeg[idx] = 0; g_cursor[idx] = 0; }
    if (idx >= NCH * NCH) return;
    int nn = idx & 127, kk = idx >> 7;
    int o = nn * NCH + kk;
    float v1 = W1[idx], v2 = W2[idx];
    __nv_bfloat16 h1 = __float2bfloat16(v1);
    __nv_bfloat16 h2 = __float2bfloat16(v2);
    g_Wt[0][o] = h1; g_Wt[1][o] = __float2bfloat16(v1 - __bfloat162float(h1));
    g_Wt[2][o] = h2; g_Wt[3][o] = __float2bfloat16(v2 - __bfloat162float(h2));
}

__global__ void k_stats(const float* __restrict__ x, const float* __restrict__ aP, int n) {
    __shared__ float4 rs[8][32];
    __shared__ float4 rq[8][32];
    int tid = threadIdx.x, c4 = tid & 31, ry = tid >> 5;
    float av = aP[0];
    float4 s = make_float4(0, 0, 0, 0), q = make_float4(0, 0, 0, 0);
    for (int base = blockIdx.x * 32; base < n; base += gridDim.x * 32) {
#pragma unroll
        for (int u = 0; u < 4; u++) {
            int r = base + ry + u * 8;
            if (r < n) {
                float4 v = ((const float4*)x)[(size_t)r * 32 + c4];
                v.x = v.x >= 0.f ? v.x : av * v.x;
                v.y = v.y >= 0.f ? v.y : av * v.y;
                v.z = v.z >= 0.f ? v.z : av * v.z;
                v.w = v.w >= 0.f ? v.w : av * v.w;
                s.x += v.x; s.y += v.y; s.z += v.z; s.w += v.w;
                q.x += v.x * v.x; q.y += v.y * v.y; q.z += v.z * v.z; q.w += v.w * v.w;
            }
        }
    }
    rs[ry][c4] = s; rq[ry][c4] = q;
    __syncthreads();
    if (ry == 0) {
        float4 S = rs[0][c4], Q = rq[0][c4];
#pragma unroll
        for (int i = 1; i < 8; i++) {
            float4 a = rs[i][c4], b = rq[i][c4];
            S.x += a.x; S.y += a.y; S.z += a.z; S.w += a.w;
            Q.x += b.x; Q.y += b.y; Q.z += b.z; Q.w += b.w;
        }
        atomicAdd(&g_sum[c4 * 4 + 0], S.x); atomicAdd(&g_sum[c4 * 4 + 1], S.y);
        atomicAdd(&g_sum[c4 * 4 + 2], S.z); atomicAdd(&g_sum[c4 * 4 + 3], S.w);
        atomicAdd(&g_sumsq[c4 * 4 + 0], Q.x); atomicAdd(&g_sumsq[c4 * 4 + 1], Q.y);
        atomicAdd(&g_sumsq[c4 * 4 + 2], Q.z); atomicAdd(&g_sumsq[c4 * 4 + 3], Q.w);
    }
}

__global__ void k_finalize(const float* __restrict__ gamma, const float* __restrict__ beta, int n) {
    int c = threadIdx.x;
    if (c >= NCH) return;
    float invn = 1.0f / (float)n;
    float mean = g_sum[c] * invn;
    float var  = g_sumsq[c] * invn - mean * mean;
    float sc   = gamma[c] * rsqrtf(var + 1e-5f);
    g_scale[c] = sc;
    g_shift[c] = beta[c] - mean * sc;
}

__global__ void k_count(const int* __restrict__ dst, int e) {
    int i = blockIdx.x * blockDim.x + threadIdx.x;
    if (i < e) atomicAdd(&g_indeg[dst[i]], 1);
}

__global__ void k_scan1(int n) {
    __shared__ int sh[CHUNK];
    int i = blockIdx.x * CHUNK + threadIdx.x;
    sh[threadIdx.x] = (i < n) ? g_indeg[i] : 0;
    __syncthreads();
    for (int s = CHUNK / 2; s > 0; s >>= 1) {
        if (threadIdx.x < s) sh[threadIdx.x] += sh[threadIdx.x + s];
        __syncthreads();
    }
    if (threadIdx.x == 0) g_bsum[blockIdx.x] = sh[0];
}
__global__ void k_scan2() {
    __shared__ int sh[CHUNK];
    int t = threadIdx.x;
    sh[t] = (t < NCHUNK) ? g_bsum[t] : 0;
    __syncthreads();
    for (int d = 1; d < CHUNK; d <<= 1) {
        int v = (t >= d) ? sh[t - d] : 0;
        __syncthreads();
        sh[t] += v;
        __syncthreads();
    }
    if (t < NCHUNK) g_bbase[t] = (t == 0) ? 0 : sh[t - 1];
}
// scan3 + dinv fused
__global__ void k_scan3(int n) {
    __shared__ int sh[CHUNK];
    int t = threadIdx.x;
    int i = blockIdx.x * CHUNK + t;
    int v0 = (i < n) ? g_indeg[i] : 0;
    sh[t] = v0;
    __syncthreads();
    for (int d = 1; d < CHUNK; d <<= 1) {
        int v = (t >= d) ? sh[t - d] : 0;
        __syncthreads();
        sh[t] += v;
        __syncthreads();
    }
    if (i < n) {
        g_rowptr[i] = g_bbase[blockIdx.x] + sh[t] - v0;
        g_dinv[i] = rsqrtf((float)(v0 + 1));
    }
}
__global__ void k_fill(const int* __restrict__ src, const int* __restrict__ dst, int e) {
    int i = blockIdx.x * blockDim.x + threadIdx.x;
    if (i >= e) return;
    int d = dst[i];
    int pos = g_rowptr[d] + atomicAdd(&g_cursor[d], 1);
    g_esrc[pos] = src[i];
}

// ---------------- HMMA / async helpers ----------------
__device__ __forceinline__ void mma16816(float* c, const uint32_t* a, const uint32_t* b) {
    asm volatile(
        "mma.sync.aligned.m16n8k16.row.col.f32.bf16.bf16.f32 "
        "{%0,%1,%2,%3}, {%4,%5,%6,%7}, {%8,%9}, {%0,%1,%2,%3};"
        : "+f"(c[0]), "+f"(c[1]), "+f"(c[2]), "+f"(c[3])
        : "r"(a[0]), "r"(a[1]), "r"(a[2]), "r"(a[3]), "r"(b[0]), "r"(b[1]));
}
__device__ __forceinline__ void ldsm4(uint32_t* r, uint32_t addr) {
    asm volatile("ldmatrix.sync.aligned.m8n8.x4.shared.b16 {%0,%1,%2,%3}, [%4];"
                 : "=r"(r[0]), "=r"(r[1]), "=r"(r[2]), "=r"(r[3]) : "r"(addr));
}
__device__ __forceinline__ uint32_t pack_bf2(float x, float y) {
    __nv_bfloat162 h = __floats2bfloat162_rn(x, y);
    return *(uint32_t*)&h;
}
__device__ __forceinline__ void cpasync16(uint32_t dst, const void* src, int srcsz) {
    asm volatile("cp.async.cg.shared.global [%0], [%1], 16, %2;"
                 :: "r"(dst), "l"(src), "r"(srcsz));
}
#define CPASYNC_COMMIT() asm volatile("cp.async.commit_group;" ::: "memory")
#define CPASYNC_WAIT0()  asm volatile("cp.async.wait_group 0;" ::: "memory")

// ---------------- persistent GEMM with cp.async staged A ----------------
// g_h = f(A) @ W, 3-term compensated bf16 product. MODE 0: BN(PReLU), MODE 1: PReLU.
template <int MODE>
__global__ void __launch_bounds__(256)
k_mma(const float* __restrict__ Ain,
      const __nv_bfloat16* __restrict__ Whi, const __nv_bfloat16* __restrict__ Wlo,
      const float* __restrict__ aP, int n, int ntiles)
{
    extern __shared__ char sm[];
    const int AH = 0, AL = 128 * SKB, WH = 2 * 128 * SKB, WL = 3 * 128 * SKB;
    const int STAGE = 4 * 128 * SKB;
    int tid = threadIdx.x;
    float av = aP[0];
    uint32_t sbase = (uint32_t)__cvta_generic_to_shared(sm);

    // ---- W splits: once per CTA ----
    {
        const uint4* wh4 = (const uint4*)Whi;
        const uint4* wl4 = (const uint4*)Wlo;
#pragma unroll
        for (int i = 0; i < 8; i++) {
            int idx = tid + i * 256;
            int rw = idx >> 4, cm = idx & 15;
            *(uint4*)(sm + WH + rw * SKB + cm * 16) = wh4[idx];
            *(uint4*)(sm + WL + rw * SKB + cm * 16) = wl4[idx];
        }
    }

    int warp = tid >> 5, lane = tid & 31;
    int g = lane >> 2, tg = lane & 3;
    int m0 = (warp & 3) * 32;
    int n0 = (warp >> 2) * 64;
    int sel = lane >> 3, rowin = lane & 7;

    uint32_t aoffA = (uint32_t)((m0 + (sel & 1) * 8 + rowin) * SKB + (sel >> 1) * 16);
    uint32_t boffB = (uint32_t)((n0 + (sel >> 1) * 8 + rowin) * SKB + (sel & 1) * 16);

    int rl = tid & 127, half = tid >> 7;   // transform mapping (stage reads conflict-free)

    // ---- prologue: stage first tile ----
    int t = blockIdx.x;
    if (t < ntiles) {
        int row0 = t * 128;
#pragma unroll
        for (int i = 0; i < 16; i++) {
            int c = tid + i * 256;
            int row = c >> 5, col = c & 31;
            int gr = row0 + row;
            cpasync16(sbase + STAGE + row * STG_STRIDE + col * 16,
                      (const char*)Ain + (size_t)gr * 512 + col * 16,
                      (gr < n) ? 16 : 0);
        }
    }
    CPASYNC_COMMIT();

    for (; t < ntiles; t += gridDim.x) {
        int row0 = t * 128;
        CPASYNC_WAIT0();
        __syncthreads();   // stage(tile t) visible to all

        // ---- transform stage -> AH/AL (hi/lo split) ----
        {
            const char* sp = sm + STAGE + rl * STG_STRIDE + half * 256;
            char* dh = sm + AH + rl * SKB + half * 128;
            char* dl = sm + AL + rl * SKB + half * 128;
#pragma unroll
            for (int q = 0; q < 16; q++) {
                float4 v = *(const float4*)(sp + q * 16);
                v.x = v.x >= 0.f ? v.x : av * v.x;
                v.y = v.y >= 0.f ? v.y : av * v.y;
                v.z = v.z >= 0.f ? v.z : av * v.z;
                v.w = v.w >= 0.f ? v.w : av * v.w;
                if (MODE == 0) {
                    float4 sc = ((const float4*)g_scale)[half * 16 + q];
                    float4 sf = ((const float4*)g_shift)[half * 16 + q];
                    v.x = fmaf(v.x, sc.x, sf.x); v.y = fmaf(v.y, sc.y, sf.y);
                    v.z = fmaf(v.z, sc.z, sf.z); v.w = fmaf(v.w, sc.w, sf.w);
                }
                __nv_bfloat16 hx = __float2bfloat16(v.x), hy = __float2bfloat16(v.y);
                __nv_bfloat16 hz = __float2bfloat16(v.z), hw = __float2bfloat16(v.w);
                uint2 hi; hi.x = pack_bf2(v.x, v.y); hi.y = pack_bf2(v.z, v.w);
                float lx = v.x - __bfloat162float(hx), ly = v.y - __bfloat162float(hy);
                float lz = v.z - __bfloat162float(hz), lw = v.w - __bfloat162float(hw);
                uint2 lo; lo.x = pack_bf2(lx, ly); lo.y = pack_bf2(lz, lw);
                *(uint2*)(dh + q * 8) = hi;
                *(uint2*)(dl + q * 8) = lo;
            }
        }
        __syncthreads();   // stage consumed; AH/AL ready

        // ---- prefetch next tile into stage (overlaps compute) ----
        int tn = t + gridDim.x;
        if (tn < ntiles) {
            int rown = tn * 128;
#pragma unroll
            for (int i = 0; i < 16; i++) {
                int c = tid + i * 256;
                int row = c >> 5, col = c & 31;
                int gr = rown + row;
                cpasync16(sbase + STAGE + row * STG_STRIDE + col * 16,
                          (const char*)Ain + (size_t)gr * 512 + col * 16,
                          (gr < n) ? 16 : 0);
            }
        }
        CPASYNC_COMMIT();

        // ---- compute (3-term) ----
        float acc[2][8][4];
#pragma unroll
        for (int mt = 0; mt < 2; mt++)
#pragma unroll
            for (int j = 0; j < 8; j++)
#pragma unroll
                for (int v = 0; v < 4; v++) acc[mt][j][v] = 0.f;

#pragma unroll
        for (int kc = 0; kc < 8; kc++) {
            uint32_t kb = kc * 32;
            uint32_t ah[2][4], al[2][4];
#pragma unroll
            for (int mt = 0; mt < 2; mt++) {
                ldsm4(ah[mt], sbase + AH + aoffA + mt * (16 * SKB) + kb);
                ldsm4(al[mt], sbase + AL + aoffA + mt * (16 * SKB) + kb);
            }
#pragma unroll
            for (int jp = 0; jp < 4; jp++) {
                uint32_t bh[4], bl[4];
                ldsm4(bh, sbase + WH + boffB + jp * (16 * SKB) + kb);
                ldsm4(bl, sbase + WL + boffB + jp * (16 * SKB) + kb);
#pragma unroll
                for (int hf = 0; hf < 2; hf++) {
                    int j = jp * 2 + hf;
#pragma unroll
                    for (int mt = 0; mt < 2; mt++) {
                        mma16816(acc[mt][j], ah[mt], bh + hf * 2);
                        mma16816(acc[mt][j], ah[mt], bl + hf * 2);
                        mma16816(acc[mt][j], al[mt], bh + hf * 2);
                    }
                }
            }
        }

        // ---- epilogue ----
#pragma unroll
        for (int mt = 0; mt < 2; mt++) {
            int rA = row0 + m0 + mt * 16 + g;
            int rB = rA + 8;
#pragma unroll
            for (int j = 0; j < 8; j++) {
                int col = n0 + j * 8 + 2 * tg;
                if (rA < n)
                    *(float2*)(g_h + (size_t)rA * NCH + col) = make_float2(acc[mt][j][0], acc[mt][j][1]);
                if (rB < n)
                    *(float2*)(g_h + (size_t)rB * NCH + col) = make_float2(acc[mt][j][2], acc[mt][j][3]);
            }
        }
        __syncthreads();   // AH/AL free for next transform
    }
}

// ---------------- CSR gather: 2-way software-pipelined ----------------
__global__ void k_gather(const float* __restrict__ bvec, float* __restrict__ out, int n) {
    int node = (blockIdx.x * blockDim.x + threadIdx.x) >> 5;
    int lane = threadIdx.x & 31;
    if (node >= n) return;
    int off = g_rowptr[node];
    int cnt = g_indeg[node];
    float dr = g_dinv[node];
    float inv = dr * dr;
    float4 hv = ((const float4*)(g_h + (size_t)node * NCH))[lane];
    float4 bb = ((const float4*)bvec)[lane];
    float4 acc = make_float4(fmaf(hv.x, inv, bb.x), fmaf(hv.y, inv, bb.y),
                             fmaf(hv.z, inv, bb.z), fmaf(hv.w, inv, bb.w));
    int j = 0;
    for (; j + 2 <= cnt; j += 2) {
        int sa = __ldg(g_esrc + off + j);
        int sb = __ldg(g_esrc + off + j + 1);
        float ca = __ldg(g_dinv + sa) * dr;
        float cb = __ldg(g_dinv + sb) * dr;
        float4 va = __ldg(((const float4*)(g_h + (size_t)sa * NCH)) + lane);
        float4 vb = __ldg(((const float4*)(g_h + (size_t)sb * NCH)) + lane);
        acc.x = fmaf(va.x, ca, acc.x); acc.y = fmaf(va.y, ca, acc.y);
        acc.z = fmaf(va.z, ca, acc.z); acc.w = fmaf(va.w, ca, acc.w);
        acc.x = fmaf(vb.x, cb, acc.x); acc.y = fmaf(vb.y, cb, acc.y);
        acc.z = fmaf(vb.z, cb, acc.z); acc.w = fmaf(vb.w, cb, acc.w);
    }
    if (j < cnt) {
        int s = __ldg(g_esrc + off + j);
        float c = __ldg(g_dinv + s) * dr;
        float4 sv = __ldg(((const float4*)(g_h + (size_t)s * NCH)) + lane);
        acc.x = fmaf(sv.x, c, acc.x); acc.y = fmaf(sv.y, c, acc.y);
        acc.z = fmaf(sv.z, c, acc.z); acc.w = fmaf(sv.w, c, acc.w);
    }
    ((float4*)(out + (size_t)node * NCH))[lane] = acc;
}

// ---------------- launch ----------------
extern "C" void kernel_launch(void* const* d_in, const int* in_sizes, int n_in,
                              void* d_out, int out_size) {
    const float* x     = (const float*)d_in[0];
    const int*   ei    = (const int*)  d_in[1];
    const float* a1    = (const float*)d_in[2];
    const float* gamma = (const float*)d_in[3];
    const float* beta  = (const float*)d_in[4];
    const float* W1    = (const float*)d_in[5];
    const float* b1    = (const float*)d_in[6];
    const float* a2    = (const float*)d_in[7];
    const float* W2    = (const float*)d_in[8];
    const float* b2    = (const float*)d_in[9];
    float* out = (float*)d_out;

    int n = in_sizes[0] / NCH;
    int e = in_sizes[1] / 2;
    const int* src = ei;
    const int* dst = ei + e;

    const int SMEM = 4 * 128 * SKB + 128 * STG_STRIDE;   // 139264 + 67584 = 206848
    cudaFuncSetAttribute(k_mma<0>, cudaFuncAttributeMaxDynamicSharedMemorySize, SMEM);
    cudaFuncSetAttribute(k_mma<1>, cudaFuncAttributeMaxDynamicSharedMemorySize, SMEM);

    float* accPtr = nullptr;
    cudaGetSymbolAddress((void**)&accPtr, g_acc);
    __nv_bfloat16* wtPtr = nullptr;
    cudaGetSymbolAddress((void**)&wtPtr, g_Wt);

    int ntiles = (n + 127) / 128;
    int gatBlocks = (int)(((long long)n * 32 + 255) / 256);

    // 1-3: BN stats path (convW also zeroes CSR counters)
    k_convW<<<(n + 255) / 256, 256>>>(W1, W2, n);
    k_stats<<<1184, 256>>>(x, a1, n);
    k_finalize<<<1, 128>>>(gamma, beta, n);
    // 4: conv1 GEMM (ncu profile slot), persistent + staged
    k_mma<0><<<MMA_GRID, 256, SMEM>>>(x, wtPtr + 0 * NCH * NCH, wtPtr + 1 * NCH * NCH, a1, n, ntiles);
    // CSR build
    k_count<<<(e + 255) / 256, 256>>>(dst, e);
    k_scan1<<<NCHUNK, CHUNK>>>(n);
    k_scan2<<<1, CHUNK>>>();
    k_scan3<<<NCHUNK, CHUNK>>>(n);
    k_fill<<<(e + 255) / 256, 256>>>(src, dst, e);
    // conv1 aggregate
    k_gather<<<gatBlocks, 256>>>(b1, accPtr, n);
    // conv2
    k_mma<1><<<MMA_GRID, 256, SMEM>>>(accPtr, wtPtr + 2 * NCH * NCH, wtPtr + 3 * NCH * NCH, a2, n, ntiles);
    k_gather<<<gatBlocks, 256>>>(b2, out, n);
}

// round 16
// speedup vs baseline: 1.1954x; 1.0057x over previous
#include <cuda_runtime.h>
#include <cuda_bf16.h>
#include <cstdint>

#define NNODES 200000
#define NEDGES 600000
#define NCH    128
#define SK     136            // padded bf16 row stride
#define SKB    (SK * 2)
#define CHUNK  512
#define NCHUNK ((NNODES + CHUNK - 1) / CHUNK)   // 391
#define MMA_GRID 152
#define STG_STRIDE 528        // staged f32 row stride (16B-aligned, low-conflict)

// ---------------- scratch ----------------
__device__ float g_h[(size_t)NNODES * NCH];
__device__ float g_acc[(size_t)NNODES * NCH];
__device__ float g_dinv[NNODES];
__device__ int   g_indeg[NNODES];
__device__ int   g_cursor[NNODES];
__device__ int   g_rowptr[NNODES];
__device__ int   g_bsum[CHUNK];
__device__ int   g_bbase[CHUNK];
__device__ int   g_esrc[NEDGES];
__device__ float g_sum[NCH];
__device__ float g_sumsq[NCH];
__device__ float g_scale[NCH];
__device__ float g_shift[NCH];
__device__ __nv_bfloat16 g_Wt[4][NCH * NCH];   // W1hi W1lo W2hi W2lo, [n][k]

// ---------------- prep ----------------
__global__ void k_convW(const float* __restrict__ W1, const float* __restrict__ W2, int n) {
    int idx = blockIdx.x * blockDim.x + threadIdx.x;
    if (idx < NCH) { g_sum[idx] = 0.f; g_sumsq[idx] = 0.f; }
    if (idx < n) { g_indeg[idx] = 0; g_cursor[idx] = 0; }
    if (idx >= NCH * NCH) return;
    int nn = idx & 127, kk = idx >> 7;
    int o = nn * NCH + kk;
    float v1 = W1[idx], v2 = W2[idx];
    __nv_bfloat16 h1 = __float2bfloat16(v1);
    __nv_bfloat16 h2 = __float2bfloat16(v2);
    g_Wt[0][o] = h1; g_Wt[1][o] = __float2bfloat16(v1 - __bfloat162float(h1));
    g_Wt[2][o] = h2; g_Wt[3][o] = __float2bfloat16(v2 - __bfloat162float(h2));
}

__global__ void k_stats(const float* __restrict__ x, const float* __restrict__ aP, int n) {
    __shared__ float4 rs[8][32];
    __shared__ float4 rq[8][32];
    int tid = threadIdx.x, c4 = tid & 31, ry = tid >> 5;
    float av = aP[0];
    float4 s = make_float4(0, 0, 0, 0), q = make_float4(0, 0, 0, 0);
    for (int base = blockIdx.x * 32; base < n; base += gridDim.x * 32) {
#pragma unroll
        for (int u = 0; u < 4; u++) {
            int r = base + ry + u * 8;
            if (r < n) {
                float4 v = ((const float4*)x)[(size_t)r * 32 + c4];
                v.x = v.x >= 0.f ? v.x : av * v.x;
                v.y = v.y >= 0.f ? v.y : av * v.y;
                v.z = v.z >= 0.f ? v.z : av * v.z;
                v.w = v.w >= 0.f ? v.w : av * v.w;
                s.x += v.x; s.y += v.y; s.z += v.z; s.w += v.w;
                q.x += v.x * v.x; q.y += v.y * v.y; q.z += v.z * v.z; q.w += v.w * v.w;
            }
        }
    }
    rs[ry][c4] = s; rq[ry][c4] = q;
    __syncthreads();
    if (ry == 0) {
        float4 S = rs[0][c4], Q = rq[0][c4];
#pragma unroll
        for (int i = 1; i < 8; i++) {
            float4 a = rs[i][c4], b = rq[i][c4];
            S.x += a.x; S.y += a.y; S.z += a.z; S.w += a.w;
            Q.x += b.x; Q.y += b.y; Q.z += b.z; Q.w += b.w;
        }
        atomicAdd(&g_sum[c4 * 4 + 0], S.x); atomicAdd(&g_sum[c4 * 4 + 1], S.y);
        atomicAdd(&g_sum[c4 * 4 + 2], S.z); atomicAdd(&g_sum[c4 * 4 + 3], S.w);
        atomicAdd(&g_sumsq[c4 * 4 + 0], Q.x); atomicAdd(&g_sumsq[c4 * 4 + 1], Q.y);
        atomicAdd(&g_sumsq[c4 * 4 + 2], Q.z); atomicAdd(&g_sumsq[c4 * 4 + 3], Q.w);
    }
}

__global__ void k_finalize(const float* __restrict__ gamma, const float* __restrict__ beta, int n) {
    int c = threadIdx.x;
    if (c >= NCH) return;
    float invn = 1.0f / (float)n;
    float mean = g_sum[c] * invn;
    float var  = g_sumsq[c] * invn - mean * mean;
    float sc   = gamma[c] * rsqrtf(var + 1e-5f);
    g_scale[c] = sc;
    g_shift[c] = beta[c] - mean * sc;
}

__global__ void k_count(const int* __restrict__ dst, int e) {
    int i = blockIdx.x * blockDim.x + threadIdx.x;
    if (i < e) atomicAdd(&g_indeg[dst[i]], 1);
}

__global__ void k_scan1(int n) {
    __shared__ int sh[CHUNK];
    int i = blockIdx.x * CHUNK + threadIdx.x;
    sh[threadIdx.x] = (i < n) ? g_indeg[i] : 0;
    __syncthreads();
    for (int s = CHUNK / 2; s > 0; s >>= 1) {
        if (threadIdx.x < s) sh[threadIdx.x] += sh[threadIdx.x + s];
        __syncthreads();
    }
    if (threadIdx.x == 0) g_bsum[blockIdx.x] = sh[0];
}
__global__ void k_scan2() {
    __shared__ int sh[CHUNK];
    int t = threadIdx.x;
    sh[t] = (t < NCHUNK) ? g_bsum[t] : 0;
    __syncthreads();
    for (int d = 1; d < CHUNK; d <<= 1) {
        int v = (t >= d) ? sh[t - d] : 0;
        __syncthreads();
        sh[t] += v;
        __syncthreads();
    }
    if (t < NCHUNK) g_bbase[t] = (t == 0) ? 0 : sh[t - 1];
}
// scan3 + dinv fused
__global__ void k_scan3(int n) {
    __shared__ int sh[CHUNK];
    int t = threadIdx.x;
    int i = blockIdx.x * CHUNK + t;
    int v0 = (i < n) ? g_indeg[i] : 0;
    sh[t] = v0;
    __syncthreads();
    for (int d = 1; d < CHUNK; d <<= 1) {
        int v = (t >= d) ? sh[t - d] : 0;
        __syncthreads();
        sh[t] += v;
        __syncthreads();
    }
    if (i < n) {
        g_rowptr[i] = g_bbase[blockIdx.x] + sh[t] - v0;
        g_dinv[i] = rsqrtf((float)(v0 + 1));
    }
}
__global__ void k_fill(const int* __restrict__ src, const int* __restrict__ dst, int e) {
    int i = blockIdx.x * blockDim.x + threadIdx.x;
    if (i >= e) return;
    int d = dst[i];
    int pos = g_rowptr[d] + atomicAdd(&g_cursor[d], 1);
    g_esrc[pos] = src[i];
}

// ---------------- HMMA / async helpers ----------------
__device__ __forceinline__ void mma16816(float* c, const uint32_t* a, const uint32_t* b) {
    asm volatile(
        "mma.sync.aligned.m16n8k16.row.col.f32.bf16.bf16.f32 "
        "{%0,%1,%2,%3}, {%4,%5,%6,%7}, {%8,%9}, {%0,%1,%2,%3};"
        : "+f"(c[0]), "+f"(c[1]), "+f"(c[2]), "+f"(c[3])
        : "r"(a[0]), "r"(a[1]), "r"(a[2]), "r"(a[3]), "r"(b[0]), "r"(b[1]));
}
__device__ __forceinline__ void ldsm4(uint32_t* r, uint32_t addr) {
    asm volatile("ldmatrix.sync.aligned.m8n8.x4.shared.b16 {%0,%1,%2,%3}, [%4];"
                 : "=r"(r[0]), "=r"(r[1]), "=r"(r[2]), "=r"(r[3]) : "r"(addr));
}
__device__ __forceinline__ uint32_t pack_bf2(float x, float y) {
    __nv_bfloat162 h = __floats2bfloat162_rn(x, y);
    return *(uint32_t*)&h;
}
__device__ __forceinline__ void cpasync16(uint32_t dst, const void* src, int srcsz) {
    asm volatile("cp.async.cg.shared.global [%0], [%1], 16, %2;"
                 :: "r"(dst), "l"(src), "r"(srcsz));
}
#define CPASYNC_COMMIT() asm volatile("cp.async.commit_group;" ::: "memory")
#define CPASYNC_WAIT0()  asm volatile("cp.async.wait_group 0;" ::: "memory")

// ---------------- persistent GEMM with cp.async staged A + pipelined fragments ----------------
template <int MODE>
__global__ void __launch_bounds__(256)
k_mma(const float* __restrict__ Ain,
      const __nv_bfloat16* __restrict__ Whi, const __nv_bfloat16* __restrict__ Wlo,
      const float* __restrict__ aP, int n, int ntiles)
{
    extern __shared__ char sm[];
    const int AH = 0, AL = 128 * SKB, WH = 2 * 128 * SKB, WL = 3 * 128 * SKB;
    const int STAGE = 4 * 128 * SKB;
    int tid = threadIdx.x;
    float av = aP[0];
    uint32_t sbase = (uint32_t)__cvta_generic_to_shared(sm);

    // ---- W splits: once per CTA ----
    {
        const uint4* wh4 = (const uint4*)Whi;
        const uint4* wl4 = (const uint4*)Wlo;
#pragma unroll
        for (int i = 0; i < 8; i++) {
            int idx = tid + i * 256;
            int rw = idx >> 4, cm = idx & 15;
            *(uint4*)(sm + WH + rw * SKB + cm * 16) = wh4[idx];
            *(uint4*)(sm + WL + rw * SKB + cm * 16) = wl4[idx];
        }
    }

    int warp = tid >> 5, lane = tid & 31;
    int g = lane >> 2, tg = lane & 3;
    int m0 = (warp & 3) * 32;
    int n0 = (warp >> 2) * 64;
    int sel = lane >> 3, rowin = lane & 7;

    uint32_t aoffA = (uint32_t)((m0 + (sel & 1) * 8 + rowin) * SKB + (sel >> 1) * 16);
    uint32_t boffB = (uint32_t)((n0 + (sel >> 1) * 8 + rowin) * SKB + (sel & 1) * 16);

    int rl = tid & 127, half = tid >> 7;

    // ---- prologue: stage first tile ----
    int t = blockIdx.x;
    if (t < ntiles) {
        int row0 = t * 128;
#pragma unroll
        for (int i = 0; i < 16; i++) {
            int c = tid + i * 256;
            int row = c >> 5, col = c & 31;
            int gr = row0 + row;
            cpasync16(sbase + STAGE + row * STG_STRIDE + col * 16,
                      (const char*)Ain + (size_t)gr * 512 + col * 16,
                      (gr < n) ? 16 : 0);
        }
    }
    CPASYNC_COMMIT();

    for (; t < ntiles; t += gridDim.x) {
        int row0 = t * 128;
        CPASYNC_WAIT0();
        __syncthreads();

        // ---- transform stage -> AH/AL ----
        {
            const char* sp = sm + STAGE + rl * STG_STRIDE + half * 256;
            char* dh = sm + AH + rl * SKB + half * 128;
            char* dl = sm + AL + rl * SKB + half * 128;
#pragma unroll
            for (int q = 0; q < 16; q++) {
                float4 v = *(const float4*)(sp + q * 16);
                v.x = v.x >= 0.f ? v.x : av * v.x;
                v.y = v.y >= 0.f ? v.y : av * v.y;
                v.z = v.z >= 0.f ? v.z : av * v.z;
                v.w = v.w >= 0.f ? v.w : av * v.w;
                if (MODE == 0) {
                    float4 sc = ((const float4*)g_scale)[half * 16 + q];
                    float4 sf = ((const float4*)g_shift)[half * 16 + q];
                    v.x = fmaf(v.x, sc.x, sf.x); v.y = fmaf(v.y, sc.y, sf.y);
                    v.z = fmaf(v.z, sc.z, sf.z); v.w = fmaf(v.w, sc.w, sf.w);
                }
                __nv_bfloat16 hx = __float2bfloat16(v.x), hy = __float2bfloat16(v.y);
                __nv_bfloat16 hz = __float2bfloat16(v.z), hw = __float2bfloat16(v.w);
                uint2 hi; hi.x = pack_bf2(v.x, v.y); hi.y = pack_bf2(v.z, v.w);
                float lx = v.x - __bfloat162float(hx), ly = v.y - __bfloat162float(hy);
                float lz = v.z - __bfloat162float(hz), lw = v.w - __bfloat162float(hw);
                uint2 lo; lo.x = pack_bf2(lx, ly); lo.y = pack_bf2(lz, lw);
                *(uint2*)(dh + q * 8) = hi;
                *(uint2*)(dl + q * 8) = lo;
            }
        }
        __syncthreads();

        // ---- prefetch next tile into stage ----
        int tn = t + gridDim.x;
        if (tn < ntiles) {
            int rown = tn * 128;
#pragma unroll
            for (int i = 0; i < 16; i++) {
                int c = tid + i * 256;
                int row = c >> 5, col = c & 31;
                int gr = rown + row;
                cpasync16(sbase + STAGE + row * STG_STRIDE + col * 16,
                          (const char*)Ain + (size_t)gr * 512 + col * 16,
                          (gr < n) ? 16 : 0);
            }
        }
        CPASYNC_COMMIT();

        // ---- compute (3-term), software-pipelined fragments ----
        float acc[2][8][4];
#pragma unroll
        for (int mt = 0; mt < 2; mt++)
#pragma unroll
            for (int j = 0; j < 8; j++)
#pragma unroll
                for (int v = 0; v < 4; v++) acc[mt][j][v] = 0.f;

        uint32_t ah[2][2][4], al[2][2][4];   // [parity][mt]
        uint32_t bh[2][4], bl[2][4];         // [parity]

#pragma unroll
        for (int mt = 0; mt < 2; mt++) {
            ldsm4(ah[0][mt], sbase + AH + aoffA + mt * (16 * SKB));
            ldsm4(al[0][mt], sbase + AL + aoffA + mt * (16 * SKB));
        }
        ldsm4(bh[0], sbase + WH + boffB);
        ldsm4(bl[0], sbase + WL + boffB);

#pragma unroll
        for (int kc = 0; kc < 8; kc++) {
            const int pa = kc & 1;
            if (kc < 7) {
#pragma unroll
                for (int mt = 0; mt < 2; mt++) {
                    ldsm4(ah[pa ^ 1][mt], sbase + AH + aoffA + mt * (16 * SKB) + (kc + 1) * 32);
                    ldsm4(al[pa ^ 1][mt], sbase + AL + aoffA + mt * (16 * SKB) + (kc + 1) * 32);
                }
            }
#pragma unroll
            for (int jp = 0; jp < 4; jp++) {
                const int pb = jp & 1;
                if (jp < 3) {
                    ldsm4(bh[pb ^ 1], sbase + WH + boffB + (jp + 1) * (16 * SKB) + kc * 32);
                    ldsm4(bl[pb ^ 1], sbase + WL + boffB + (jp + 1) * (16 * SKB) + kc * 32);
                } else if (kc < 7) {
                    ldsm4(bh[pb ^ 1], sbase + WH + boffB + (kc + 1) * 32);
                    ldsm4(bl[pb ^ 1], sbase + WL + boffB + (kc + 1) * 32);
                }
#pragma unroll
                for (int hf = 0; hf < 2; hf++) {
                    int j = jp * 2 + hf;
#pragma unroll
                    for (int mt = 0; mt < 2; mt++) {
                        mma16816(acc[mt][j], ah[pa][mt], bh[pb] + hf * 2);
                        mma16816(acc[mt][j], ah[pa][mt], bl[pb] + hf * 2);
                        mma16816(acc[mt][j], al[pa][mt], bh[pb] + hf * 2);
                    }
                }
            }
        }

        // ---- epilogue ----
#pragma unroll
        for (int mt = 0; mt < 2; mt++) {
            int rA = row0 + m0 + mt * 16 + g;
            int rB = rA + 8;
#pragma unroll
            for (int j = 0; j < 8; j++) {
                int col = n0 + j * 8 + 2 * tg;
                if (rA < n)
                    *(float2*)(g_h + (size_t)rA * NCH + col) = make_float2(acc[mt][j][0], acc[mt][j][1]);
                if (rB < n)
                    *(float2*)(g_h + (size_t)rB * NCH + col) = make_float2(acc[mt][j][2], acc[mt][j][3]);
            }
        }
        __syncthreads();
    }
}

// ---------------- CSR gather: 4-way software-pipelined ----------------
__global__ void k_gather(const float* __restrict__ bvec, float* __restrict__ out, int n) {
    int node = (blockIdx.x * blockDim.x + threadIdx.x) >> 5;
    int lane = threadIdx.x & 31;
    if (node >= n) return;
    int off = g_rowptr[node];
    int cnt = g_indeg[node];
    float dr = g_dinv[node];
    float inv = dr * dr;
    float4 hv = ((const float4*)(g_h + (size_t)node * NCH))[lane];
    float4 bb = ((const float4*)bvec)[lane];
    float4 acc = make_float4(fmaf(hv.x, inv, bb.x), fmaf(hv.y, inv, bb.y),
                             fmaf(hv.z, inv, bb.z), fmaf(hv.w, inv, bb.w));
    int j = 0;
    for (; j + 4 <= cnt; j += 4) {
        int sa = __ldg(g_esrc + off + j);
        int sb = __ldg(g_esrc + off + j + 1);
        int sc = __ldg(g_esrc + off + j + 2);
        int sd = __ldg(g_esrc + off + j + 3);
        float ca = __ldg(g_dinv + sa) * dr;
        float cb = __ldg(g_dinv + sb) * dr;
        float cc = __ldg(g_dinv + sc) * dr;
        float cd = __ldg(g_dinv + sd) * dr;
        float4 va = __ldg(((const float4*)(g_h + (size_t)sa * NCH)) + lane);
        float4 vb = __ldg(((const float4*)(g_h + (size_t)sb * NCH)) + lane);
        float4 vc = __ldg(((const float4*)(g_h + (size_t)sc * NCH)) + lane);
        float4 vd = __ldg(((const float4*)(g_h + (size_t)sd * NCH)) + lane);
        acc.x = fmaf(va.x, ca, acc.x); acc.y = fmaf(va.y, ca, acc.y);
        acc.z = fmaf(va.z, ca, acc.z); acc.w = fmaf(va.w, ca, acc.w);
        acc.x = fmaf(vb.x, cb, acc.x); acc.y = fmaf(vb.y, cb, acc.y);
        acc.z = fmaf(vb.z, cb, acc.z); acc.w = fmaf(vb.w, cb, acc.w);
        acc.x = fmaf(vc.x, cc, acc.x); acc.y = fmaf(vc.y, cc, acc.y);
        acc.z = fmaf(vc.z, cc, acc.z); acc.w = fmaf(vc.w, cc, acc.w);
        acc.x = fmaf(vd.x, cd, acc.x); acc.y = fmaf(vd.y, cd, acc.y);
        acc.z = fmaf(vd.z, cd, acc.z); acc.w = fmaf(vd.w, cd, acc.w);
    }
    for (; j < cnt; j++) {
        int s = __ldg(g_esrc + off + j);
        float c = __ldg(g_dinv + s) * dr;
        float4 sv = __ldg(((const float4*)(g_h + (size_t)s * NCH)) + lane);
        acc.x = fmaf(sv.x, c, acc.x); acc.y = fmaf(sv.y, c, acc.y);
        acc.z = fmaf(sv.z, c, acc.z); acc.w = fmaf(sv.w, c, acc.w);
    }
    ((float4*)(out + (size_t)node * NCH))[lane] = acc;
}

// ---------------- launch ----------------
extern "C" void kernel_launch(void* const* d_in, const int* in_sizes, int n_in,
                              void* d_out, int out_size) {
    const float* x     = (const float*)d_in[0];
    const int*   ei    = (const int*)  d_in[1];
    const float* a1    = (const float*)d_in[2];
    const float* gamma = (const float*)d_in[3];
    const float* beta  = (const float*)d_in[4];
    const float* W1    = (const float*)d_in[5];
    const float* b1    = (const float*)d_in[6];
    const float* a2    = (const float*)d_in[7];
    const float* W2    = (const float*)d_in[8];
    const float* b2    = (const float*)d_in[9];
    float* out = (float*)d_out;

    int n = in_sizes[0] / NCH;
    int e = in_sizes[1] / 2;
    const int* src = ei;
    const int* dst = ei + e;

    const int SMEM = 4 * 128 * SKB + 128 * STG_STRIDE;   // 206848 B
    cudaFuncSetAttribute(k_mma<0>, cudaFuncAttributeMaxDynamicSharedMemorySize, SMEM);
    cudaFuncSetAttribute(k_mma<1>, cudaFuncAttributeMaxDynamicSharedMemorySize, SMEM);

    float* accPtr = nullptr;
    cudaGetSymbolAddress((void**)&accPtr, g_acc);
    __nv_bfloat16* wtPtr = nullptr;
    cudaGetSymbolAddress((void**)&wtPtr, g_Wt);

    int ntiles = (n + 127) / 128;
    int gatBlocks = (int)(((long long)n * 32 + 255) / 256);

    // 1-3: BN stats path (convW also zeroes CSR counters)
    k_convW<<<(n + 255) / 256, 256>>>(W1, W2, n);
    k_stats<<<1184, 256>>>(x, a1, n);
    k_finalize<<<1, 128>>>(gamma, beta, n);
    // 4: conv1 GEMM (ncu profile slot), persistent + staged + pipelined
    k_mma<0><<<MMA_GRID, 256, SMEM>>>(x, wtPtr + 0 * NCH * NCH, wtPtr + 1 * NCH * NCH, a1, n, ntiles);
    // CSR build
    k_count<<<(e + 255) / 256, 256>>>(dst, e);
    k_scan1<<<NCHUNK, CHUNK>>>(n);
    k_scan2<<<1, CHUNK>>>();
    k_scan3<<<NCHUNK, CHUNK>>>(n);
    k_fill<<<(e + 255) / 256, 256>>>(src, dst, e);
    // conv1 aggregate
    k_gather<<<gatBlocks, 256>>>(b1, accPtr, n);
    // conv2
    k_mma<1><<<MMA_GRID, 256, SMEM>>>(accPtr, wtPtr + 2 * NCH * NCH, wtPtr + 3 * NCH * NCH, a2, n, ntiles);
    k_gather<<<gatBlocks, 256>>>(b2, out, n);
}